// round 2
// baseline (speedup 1.0000x reference)
#include <cuda_runtime.h>
#include <math.h>

#define B_    64
#define T_    2048
#define ENC   512
#define QD    256
#define AD    128
#define CH    32
#define KS    31
#define PADK  15

#define TILE_T 64
#define KC     32

// Scratch (static device globals — no allocation)
__device__ float g_query[B_ * AD];
__device__ float g_W2[KS * AD];
__device__ float g_bias[AD];
__device__ float g_energy[B_ * T_];

// ---------------------------------------------------------------------------
// prep 1: query[b,a] = dec[b,:] @ Wq[:,a]
// ---------------------------------------------------------------------------
__global__ void prep_query_kernel(const float* __restrict__ dec,
                                  const float* __restrict__ Wq) {
    int b = blockIdx.x;
    int a = threadIdx.x;
    float s = 0.f;
    #pragma unroll 8
    for (int q = 0; q < QD; q++)
        s += dec[b * QD + q] * Wq[q * AD + a];
    g_query[b * AD + a] = s;
}

// ---------------------------------------------------------------------------
// prep 2: W2[k,a] = sum_c conv_w[c,0,k] * Wl[c,a]   (collapses conv + einsum)
//         bias[a] = sum_c conv_b[c] * Wl[c,a]
// ---------------------------------------------------------------------------
__global__ void prep_w2_kernel(const float* __restrict__ conv_w,
                               const float* __restrict__ conv_b,
                               const float* __restrict__ Wl) {
    int a = threadIdx.x;
    for (int k = 0; k < KS; k++) {
        float s = 0.f;
        #pragma unroll
        for (int c = 0; c < CH; c++)
            s += conv_w[c * KS + k] * Wl[c * AD + a];
        g_W2[k * AD + a] = s;
    }
    float sb = 0.f;
    #pragma unroll
    for (int c = 0; c < CH; c++)
        sb += conv_b[c] * Wl[c * AD + a];
    g_bias[a] = sb;
}

// ---------------------------------------------------------------------------
// main: energy[b,t] = sum_a tanh(enc[b,t,:]@Wk[:,a] + query[b,a] + loc) * v[a]
//   loc[t,a] = sum_k prev[b, t+k-15] * W2[k,a] + bias[a]
//
// Block: (t-tile of 64) x (all 128 a), 256 threads.
// Thread map: warp (0..7) owns 8 t rows; lane owns a = lane*4 + {0..3}.
// All shared arrays touched via float4 are explicitly 16B-aligned
// (plain __shared__ float arrays are only 4B-aligned -> LDS.128 trap).
// ---------------------------------------------------------------------------
__global__ __launch_bounds__(256, 3)
void energy_kernel(const float* __restrict__ enc,
                   const float* __restrict__ Wk,
                   const float* __restrict__ prev,
                   const float* __restrict__ v) {
    __shared__ float As[TILE_T][KC + 1];                      // scalar access only
    __shared__ __align__(16) float Bs[KC][AD];                // 32 x 128
    __shared__ __align__(16) float W2s[KS][AD];               // 31 x 128
    __shared__ float prevs[TILE_T + KS - 1];                  // 94, scalar access
    __shared__ __align__(16) float vs[AD];
    __shared__ __align__(16) float qs[AD];
    __shared__ __align__(16) float bsm[AD];

    const int b    = blockIdx.y;
    const int t0   = blockIdx.x * TILE_T;
    const int tid  = threadIdx.x;
    const int lane = tid & 31;
    const int warp = tid >> 5;

    // ---- epilogue constants (visibility via first __syncthreads below) ----
    if (tid < AD) {
        vs[tid]  = v[tid];
        qs[tid]  = g_query[b * AD + tid];
        bsm[tid] = g_bias[tid];
    }
    for (int i = tid; i < KS * AD; i += 256)
        (&W2s[0][0])[i] = g_W2[i];
    if (tid < TILE_T + KS - 1) {
        int tg = t0 + tid - PADK;
        prevs[tid] = (tg >= 0 && tg < T_) ? prev[b * T_ + tg] : 0.f;
    }

    float acc[8][4];
    #pragma unroll
    for (int i = 0; i < 8; i++)
        #pragma unroll
        for (int j = 0; j < 4; j++) acc[i][j] = 0.f;

    const float* encb = enc + ((size_t)b * T_ + t0) * ENC;
    const int trow = warp * 8;   // this warp's first local t row

    for (int kc = 0; kc < ENC; kc += KC) {
        __syncthreads();
        // load A tile: 64 rows x 32 k  (2 float4 per thread, coalesced)
        #pragma unroll
        for (int r = 0; r < 2; r++) {
            int idx = tid + r * 256;
            int row = idx >> 3;
            int c4  = (idx & 7) * 4;
            float4 f = *reinterpret_cast<const float4*>(
                encb + (size_t)row * ENC + kc + c4);
            As[row][c4 + 0] = f.x;
            As[row][c4 + 1] = f.y;
            As[row][c4 + 2] = f.z;
            As[row][c4 + 3] = f.w;
        }
        // load B tile: 32 k x 128 a  (4 float4 per thread, coalesced)
        #pragma unroll
        for (int r = 0; r < 4; r++) {
            int idx = tid + r * 256;
            int k   = idx >> 5;
            int a4  = (idx & 31) * 4;
            *reinterpret_cast<float4*>(&Bs[k][a4]) =
                *reinterpret_cast<const float4*>(Wk + (size_t)(kc + k) * AD + a4);
        }
        __syncthreads();

        #pragma unroll
        for (int k = 0; k < KC; k++) {
            float4 bv = *reinterpret_cast<const float4*>(&Bs[k][lane * 4]);
            #pragma unroll
            for (int i = 0; i < 8; i++) {
                float av = As[trow + i][k];   // warp-uniform -> broadcast
                acc[i][0] += av * bv.x;
                acc[i][1] += av * bv.y;
                acc[i][2] += av * bv.z;
                acc[i][3] += av * bv.w;
            }
        }
    }

    // ---- fold location stencil into acc (same microtile, 31 k-steps) ----
    #pragma unroll 1
    for (int k = 0; k < KS; k++) {
        float4 wv = *reinterpret_cast<const float4*>(&W2s[k][lane * 4]);
        #pragma unroll
        for (int i = 0; i < 8; i++) {
            float pv = prevs[trow + i + k];   // warp-uniform -> broadcast
            acc[i][0] += pv * wv.x;
            acc[i][1] += pv * wv.y;
            acc[i][2] += pv * wv.z;
            acc[i][3] += pv * wv.w;
        }
    }

    // ---- tanh, dot with v, warp-reduce over the 128 attention dims ----
    float4 qv = *reinterpret_cast<const float4*>(&qs[lane * 4]);
    float4 bv = *reinterpret_cast<const float4*>(&bsm[lane * 4]);
    float4 vv = *reinterpret_cast<const float4*>(&vs[lane * 4]);
    #pragma unroll
    for (int i = 0; i < 8; i++) {
        float p = tanhf(acc[i][0] + qv.x + bv.x) * vv.x
                + tanhf(acc[i][1] + qv.y + bv.y) * vv.y
                + tanhf(acc[i][2] + qv.z + bv.z) * vv.z
                + tanhf(acc[i][3] + qv.w + bv.w) * vv.w;
        #pragma unroll
        for (int off = 16; off; off >>= 1)
            p += __shfl_xor_sync(0xffffffffu, p, off);
        if (lane == 0)
            g_energy[b * T_ + t0 + trow + i] = p;
    }
}

// ---------------------------------------------------------------------------
// softmax over T per batch row
// ---------------------------------------------------------------------------
__global__ __launch_bounds__(256)
void softmax_kernel(float* __restrict__ out) {
    __shared__ float red[8];
    const int b   = blockIdx.x;
    const int tid = threadIdx.x;
    const int lane = tid & 31, warp = tid >> 5;
    const float* e = g_energy + b * T_;

    // max
    float mx = -1e30f;
    for (int t = tid; t < T_; t += 256) mx = fmaxf(mx, e[t]);
    #pragma unroll
    for (int off = 16; off; off >>= 1)
        mx = fmaxf(mx, __shfl_xor_sync(0xffffffffu, mx, off));
    if (lane == 0) red[warp] = mx;
    __syncthreads();
    mx = red[lane & 7];
    #pragma unroll
    for (int off = 4; off; off >>= 1)
        mx = fmaxf(mx, __shfl_xor_sync(0xffffffffu, mx, off));

    // sum of exp
    float sum = 0.f;
    for (int t = tid; t < T_; t += 256) sum += expf(e[t] - mx);
    #pragma unroll
    for (int off = 16; off; off >>= 1)
        sum += __shfl_xor_sync(0xffffffffu, sum, off);
    __syncthreads();
    if (lane == 0) red[warp] = sum;
    __syncthreads();
    sum = red[lane & 7];
    #pragma unroll
    for (int off = 4; off; off >>= 1)
        sum += __shfl_xor_sync(0xffffffffu, sum, off);
    float inv = 1.f / sum;

    for (int t = tid; t < T_; t += 256)
        out[b * T_ + t] = expf(e[t] - mx) * inv;
}

// ---------------------------------------------------------------------------
extern "C" void kernel_launch(void* const* d_in, const int* in_sizes, int n_in,
                              void* d_out, int out_size) {
    const float* enc    = (const float*)d_in[0];   // [64,2048,512]
    const float* dec    = (const float*)d_in[1];   // [64,256]
    const float* prev   = (const float*)d_in[2];   // [64,2048]
    const float* Wq     = (const float*)d_in[3];   // [256,128]
    const float* Wk     = (const float*)d_in[4];   // [512,128]
    const float* conv_w = (const float*)d_in[5];   // [32,1,31]
    const float* conv_b = (const float*)d_in[6];   // [32]
    const float* Wl     = (const float*)d_in[7];   // [32,128]
    const float* v      = (const float*)d_in[8];   // [128]
    float* out = (float*)d_out;                    // [64,2048]

    prep_query_kernel<<<B_, AD>>>(dec, Wq);
    prep_w2_kernel<<<1, AD>>>(conv_w, conv_b, Wl);
    energy_kernel<<<dim3(T_ / TILE_T, B_), 256>>>(enc, Wk, prev, v);
    softmax_kernel<<<B_, 256>>>(out);
}

// round 5
// speedup vs baseline: 1.8392x; 1.8392x over previous
#include <cuda_runtime.h>
#include <cuda_bf16.h>
#include <cstdint>
#include <math.h>

#define B_    64
#define T_    2048
#define ENC   512
#define QD    256
#define AD    128
#define CH    32
#define KS    31
#define PADK  15

#define MT     128      // t-rows per CTA
#define KCH    64       // k per chunk (64 bf16 = 128B rows, SW128)
#define NCHUNK 9        // 8 enc chunks + 1 location chunk

// ---- dynamic smem layout (relative to 1024-aligned base) ----
#define OFF_AH   0
#define OFF_AL   16384
#define OFF_BH   32768
#define OFF_BL   49152
#define OFF_QB   65536          // 128 floats
#define OFF_VV   (OFF_QB + 512)
#define OFF_PREV (OFF_VV + 512) // 158 floats
#define OFF_PART (OFF_PREV + 640) // 2*128 floats
#define SMEM_REQ (OFF_PART + 1024 + 1024)   // + alignment slack

// ---- device scratch ----
__device__ __align__(16) float g_energy[B_ * T_];
__device__ float         g_qb[B_ * AD];
__device__ __align__(16) __nv_bfloat16 g_BT_hi[AD * ENC];
__device__ __align__(16) __nv_bfloat16 g_BT_lo[AD * ENC];
__device__ __align__(16) __nv_bfloat16 g_W2T_hi[AD * KCH];
__device__ __align__(16) __nv_bfloat16 g_W2T_lo[AD * KCH];

// ============================ helpers ============================
__device__ __forceinline__ uint32_t smem_u32(const void* p) {
    uint32_t a;
    asm("{ .reg .u64 t; cvta.to.shared.u64 t, %1; cvt.u32.u64 %0, t; }"
        : "=r"(a) : "l"(p));
    return a;
}
__device__ __forceinline__ uint32_t sw128(uint32_t off) {
    return off ^ ((off >> 3) & 0x70);
}
// pack two floats -> bf16x2 (f0 in low half)
__device__ __forceinline__ uint32_t pk(float f0, float f1) {
    uint32_t r;
    asm("cvt.rn.bf16x2.f32 %0, %1, %2;" : "=r"(r) : "f"(f1), "f"(f0));
    return r;
}
__device__ __forceinline__ void split8(const float* f, uint4& h, uint4& l) {
    float hf[8], lf[8];
    #pragma unroll
    for (int j = 0; j < 8; j++) {
        float x = f[j];
        float hv = __bfloat162float(__float2bfloat16_rn(x));
        hf[j] = hv;
        lf[j] = x - hv;
    }
    h.x = pk(hf[0], hf[1]); h.y = pk(hf[2], hf[3]);
    h.z = pk(hf[4], hf[5]); h.w = pk(hf[6], hf[7]);
    l.x = pk(lf[0], lf[1]); l.y = pk(lf[2], lf[3]);
    l.z = pk(lf[4], lf[5]); l.w = pk(lf[6], lf[7]);
}
#define LDSM4(r0, r1, r2, r3, addr)                                            \
    asm volatile("ldmatrix.sync.aligned.m8n8.x4.shared.b16 {%0,%1,%2,%3}, [%4];" \
                 : "=r"(r0), "=r"(r1), "=r"(r2), "=r"(r3) : "r"(addr))
#define MMA(c, a, b0, b1)                                                      \
    asm volatile("mma.sync.aligned.m16n8k16.row.col.f32.bf16.bf16.f32 "        \
                 "{%0,%1,%2,%3}, {%4,%5,%6,%7}, {%8,%9}, {%0,%1,%2,%3};"       \
                 : "+f"((c)[0]), "+f"((c)[1]), "+f"((c)[2]), "+f"((c)[3])      \
                 : "r"((a)[0]), "r"((a)[1]), "r"((a)[2]), "r"((a)[3]),         \
                   "r"(b0), "r"(b1))

// ============================ prep kernels ============================
__global__ void prep_bt_kernel(const float* __restrict__ Wk) {
    int n = blockIdx.x;           // 0..127
    int k = threadIdx.x;          // 0..511
    float x = Wk[(size_t)k * AD + n];
    float hv = __bfloat162float(__float2bfloat16_rn(x));
    g_BT_hi[n * ENC + k] = __float2bfloat16_rn(x);
    g_BT_lo[n * ENC + k] = __float2bfloat16_rn(x - hv);
}
__global__ void prep_w2t_kernel(const float* __restrict__ conv_w,
                                const float* __restrict__ Wl) {
    int k = blockIdx.x;           // 0..63
    int n = threadIdx.x;          // 0..127
    float w = 0.f;
    if (k < KS) {
        #pragma unroll
        for (int c = 0; c < CH; c++)
            w += conv_w[c * KS + k] * Wl[c * AD + n];
    }
    float hv = __bfloat162float(__float2bfloat16_rn(w));
    g_W2T_hi[n * KCH + k] = __float2bfloat16_rn(w);
    g_W2T_lo[n * KCH + k] = __float2bfloat16_rn(w - hv);
}
__global__ void prep_qb_kernel(const float* __restrict__ dec,
                               const float* __restrict__ Wq,
                               const float* __restrict__ conv_b,
                               const float* __restrict__ Wl) {
    int b = blockIdx.x, a = threadIdx.x;
    float s = 0.f;
    #pragma unroll 8
    for (int q = 0; q < QD; q++)
        s += dec[b * QD + q] * Wq[q * AD + a];
    #pragma unroll
    for (int c = 0; c < CH; c++)
        s += conv_b[c] * Wl[c * AD + a];
    g_qb[b * AD + a] = s;
}

// ============================ energy kernel ============================
// CTA: 128 t-rows x 128 attn dims; 8 warps (4m x 2n), warp tile 32x64.
__global__ __launch_bounds__(256, 2)
void energy_kernel(const float* __restrict__ enc,
                   const float* __restrict__ prev,
                   const float* __restrict__ v) {
    extern __shared__ char smraw[];
    const uint32_t raw = smem_u32(smraw);
    const uint32_t base = (raw + 1023u) & ~1023u;
    char* sm = smraw + (base - raw);

    const int b    = blockIdx.y;
    const int t0   = blockIdx.x * MT;
    const int tid  = threadIdx.x;
    const int lane = tid & 31;
    const int wid  = tid >> 5;
    const int warp_m  = (wid & 3) * 32;
    const int warp_n2 = (wid >> 2) * 64;

    float* qb_s = (float*)(sm + OFF_QB);
    float* vv_s = (float*)(sm + OFF_VV);
    float* pv_s = (float*)(sm + OFF_PREV);
    float* part = (float*)(sm + OFF_PART);

    if (tid < AD) {
        qb_s[tid] = g_qb[b * AD + tid];
        vv_s[tid] = v[tid];
    }
    for (int i = tid; i < MT + KS - 1; i += 256) {
        int tg = t0 + i - PADK;
        pv_s[i] = (tg >= 0 && tg < T_) ? prev[b * T_ + tg] : 0.f;
    }

    float acc[2][8][4];
    #pragma unroll
    for (int mt = 0; mt < 2; mt++)
        #pragma unroll
        for (int j = 0; j < 8; j++)
            #pragma unroll
            for (int r = 0; r < 4; r++) acc[mt][j][r] = 0.f;

    const float* encb = enc + ((size_t)b * T_ + t0) * ENC;

    for (int c = 0; c < NCHUNK; c++) {
        __syncthreads();
        // ---- fill A (hi/lo) and B (hi/lo) tiles: 128 x 64 bf16 each ----
        if (c < 8) {
            const float* src = encb + c * KCH;
            #pragma unroll
            for (int i = 0; i < 4; i++) {
                int idx = tid + i * 256;            // 0..1023
                int row = idx >> 3, g = idx & 7;
                float f[8];
                float4 f0 = *(const float4*)(src + (size_t)row * ENC + g * 8);
                float4 f1 = *(const float4*)(src + (size_t)row * ENC + g * 8 + 4);
                f[0]=f0.x; f[1]=f0.y; f[2]=f0.z; f[3]=f0.w;
                f[4]=f1.x; f[5]=f1.y; f[6]=f1.z; f[7]=f1.w;
                uint4 h, l; split8(f, h, l);
                uint32_t off = sw128((uint32_t)(row * 128 + g * 16));
                *(uint4*)(sm + OFF_AH + off) = h;
                *(uint4*)(sm + OFF_AL + off) = l;
            }
            #pragma unroll
            for (int i = 0; i < 4; i++) {
                int idx = tid + i * 256;
                int n = idx >> 3, g = idx & 7;
                uint32_t off = sw128((uint32_t)(n * 128 + g * 16));
                *(uint4*)(sm + OFF_BH + off) =
                    *(const uint4*)(g_BT_hi + n * ENC + c * KCH + g * 8);
                *(uint4*)(sm + OFF_BL + off) =
                    *(const uint4*)(g_BT_lo + n * ENC + c * KCH + g * 8);
            }
        } else {
            // location chunk: A[m][k] = prevs[m+k] (k<31 else 0), B = W2T
            #pragma unroll
            for (int i = 0; i < 4; i++) {
                int idx = tid + i * 256;
                int row = idx >> 3, g = idx & 7;
                float f[8];
                #pragma unroll
                for (int j = 0; j < 8; j++) {
                    int k = g * 8 + j;
                    f[j] = (k < KS) ? pv_s[row + k] : 0.f;
                }
                uint4 h, l; split8(f, h, l);
                uint32_t off = sw128((uint32_t)(row * 128 + g * 16));
                *(uint4*)(sm + OFF_AH + off) = h;
                *(uint4*)(sm + OFF_AL + off) = l;
            }
            #pragma unroll
            for (int i = 0; i < 4; i++) {
                int idx = tid + i * 256;
                int n = idx >> 3, g = idx & 7;
                uint32_t off = sw128((uint32_t)(n * 128 + g * 16));
                *(uint4*)(sm + OFF_BH + off) =
                    *(const uint4*)(g_W2T_hi + n * KCH + g * 8);
                *(uint4*)(sm + OFF_BL + off) =
                    *(const uint4*)(g_W2T_lo + n * KCH + g * 8);
            }
        }
        __syncthreads();

        // ---- mma over this chunk: 4 k16 steps ----
        #pragma unroll
        for (int kk = 0; kk < 4; kk++) {
            const uint32_t kb = (uint32_t)(kk * 32) + ((lane >> 4) & 1) * 16;
            uint32_t ah[2][4], al[2][4];
            #pragma unroll
            for (int mt = 0; mt < 2; mt++) {
                int row = warp_m + mt * 16 + (lane & 15);
                uint32_t off = sw128((uint32_t)(row * 128) + kb);
                LDSM4(ah[mt][0], ah[mt][1], ah[mt][2], ah[mt][3],
                      base + OFF_AH + off);
                LDSM4(al[mt][0], al[mt][1], al[mt][2], al[mt][3],
                      base + OFF_AL + off);
            }
            #pragma unroll
            for (int h = 0; h < 2; h++) {
                const uint32_t kbb = (uint32_t)(kk * 32) + ((lane >> 3) & 1) * 16;
                uint32_t bh[2][4], bl[2][4];
                #pragma unroll
                for (int q = 0; q < 2; q++) {
                    int n = warp_n2 + h * 32 + q * 16
                          + ((lane >> 4) << 3) + (lane & 7);
                    uint32_t off = sw128((uint32_t)(n * 128) + kbb);
                    LDSM4(bh[q][0], bh[q][1], bh[q][2], bh[q][3],
                          base + OFF_BH + off);
                    LDSM4(bl[q][0], bl[q][1], bl[q][2], bl[q][3],
                          base + OFF_BL + off);
                }
                #pragma unroll
                for (int mt = 0; mt < 2; mt++) {
                    #pragma unroll
                    for (int q = 0; q < 2; q++) {
                        int j = h * 4 + q * 2;
                        MMA(acc[mt][j],     ah[mt], bh[q][0], bh[q][1]);
                        MMA(acc[mt][j + 1], ah[mt], bh[q][2], bh[q][3]);
                        MMA(acc[mt][j],     ah[mt], bl[q][0], bl[q][1]);
                        MMA(acc[mt][j + 1], ah[mt], bl[q][2], bl[q][3]);
                        MMA(acc[mt][j],     al[mt], bh[q][0], bh[q][1]);
                        MMA(acc[mt][j + 1], al[mt], bh[q][2], bh[q][3]);
                    }
                }
            }
        }
    }

    // ---- epilogue: tanh + dot(v) + reduce ----
    float pr[4] = {0.f, 0.f, 0.f, 0.f};
    #pragma unroll
    for (int mt = 0; mt < 2; mt++) {
        #pragma unroll
        for (int j = 0; j < 8; j++) {
            int n0 = warp_n2 + j * 8 + 2 * (lane & 3);
            float v0 = vv_s[n0], v1 = vv_s[n0 + 1];
            float q0 = qb_s[n0], q1 = qb_s[n0 + 1];
            #pragma unroll
            for (int rh = 0; rh < 2; rh++) {     // rh=0: rows t/4, rh=1: +8
                float x0 = acc[mt][j][rh * 2]     + q0;
                float x1 = acc[mt][j][rh * 2 + 1] + q1;
                x0 = fminf(fmaxf(x0, -15.f), 15.f);
                x1 = fminf(fmaxf(x1, -15.f), 15.f);
                float e0 = __expf(2.f * x0), e1 = __expf(2.f * x1);
                float th0 = (e0 - 1.f) * __frcp_rn(e0 + 1.f);
                float th1 = (e1 - 1.f) * __frcp_rn(e1 + 1.f);
                pr[mt * 2 + rh] += th0 * v0 + th1 * v1;
            }
        }
    }
    #pragma unroll
    for (int i = 0; i < 4; i++) {
        pr[i] += __shfl_xor_sync(0xffffffffu, pr[i], 1);
        pr[i] += __shfl_xor_sync(0xffffffffu, pr[i], 2);
    }
    const int wn = wid >> 2;
    if ((lane & 3) == 0) {
        int rbase = warp_m + (lane >> 2);
        part[wn * 128 + rbase]      = pr[0];
        part[wn * 128 + rbase + 8]  = pr[1];
        part[wn * 128 + rbase + 16] = pr[2];
        part[wn * 128 + rbase + 24] = pr[3];
    }
    __syncthreads();
    if (tid < MT)
        g_energy[b * T_ + t0 + tid] = part[tid] + part[128 + tid];
}

// ============================ softmax ============================
__global__ __launch_bounds__(512)
void softmax_kernel(float* __restrict__ out) {
    __shared__ float red[16];
    const int b = blockIdx.x, tid = threadIdx.x;
    const int lane = tid & 31, warp = tid >> 5;
    const float4* e4 = (const float4*)(g_energy + b * T_);
    float4 f = e4[tid];

    float mx = fmaxf(fmaxf(f.x, f.y), fmaxf(f.z, f.w));
    #pragma unroll
    for (int o = 16; o; o >>= 1)
        mx = fmaxf(mx, __shfl_xor_sync(0xffffffffu, mx, o));
    if (lane == 0) red[warp] = mx;
    __syncthreads();
    mx = red[lane & 15];
    #pragma unroll
    for (int o = 8; o; o >>= 1)
        mx = fmaxf(mx, __shfl_xor_sync(0xffffffffu, mx, o));

    float4 ex;
    ex.x = __expf(f.x - mx); ex.y = __expf(f.y - mx);
    ex.z = __expf(f.z - mx); ex.w = __expf(f.w - mx);
    float sum = ex.x + ex.y + ex.z + ex.w;
    #pragma unroll
    for (int o = 16; o; o >>= 1)
        sum += __shfl_xor_sync(0xffffffffu, sum, o);
    __syncthreads();
    if (lane == 0) red[warp] = sum;
    __syncthreads();
    sum = red[lane & 15];
    #pragma unroll
    for (int o = 8; o; o >>= 1)
        sum += __shfl_xor_sync(0xffffffffu, sum, o);
    float inv = 1.f / sum;

    float4 o4; o4.x = ex.x*inv; o4.y = ex.y*inv; o4.z = ex.z*inv; o4.w = ex.w*inv;
    ((float4*)(out + b * T_))[tid] = o4;
}

// ============================ launch ============================
extern "C" void kernel_launch(void* const* d_in, const int* in_sizes, int n_in,
                              void* d_out, int out_size) {
    const float* enc    = (const float*)d_in[0];
    const float* dec    = (const float*)d_in[1];
    const float* prev   = (const float*)d_in[2];
    const float* Wq     = (const float*)d_in[3];
    const float* Wk     = (const float*)d_in[4];
    const float* conv_w = (const float*)d_in[5];
    const float* conv_b = (const float*)d_in[6];
    const float* Wl     = (const float*)d_in[7];
    const float* v      = (const float*)d_in[8];
    float* out = (float*)d_out;

    cudaFuncSetAttribute(energy_kernel,
                         cudaFuncAttributeMaxDynamicSharedMemorySize, SMEM_REQ);

    prep_bt_kernel<<<AD, ENC>>>(Wk);
    prep_w2t_kernel<<<KCH, AD>>>(conv_w, Wl);
    prep_qb_kernel<<<B_, AD>>>(dec, Wq, conv_b, Wl);
    energy_kernel<<<dim3(T_ / MT, B_), 256, SMEM_REQ>>>(enc, prev, v);
    softmax_kernel<<<B_, 512>>>(out);
}

// round 7
// speedup vs baseline: 2.0612x; 1.1207x over previous
#include <cuda_runtime.h>
#include <cuda_bf16.h>
#include <cstdint>
#include <math.h>

#define B_    64
#define T_    2048
#define ENC   512
#define QD    256
#define AD    128
#define CH    32
#define KS    31
#define PADK  15

#define MT     128      // t-rows per CTA
#define KCH    64       // k per chunk (64 bf16 = 128B rows, SW128)
#define NCHUNK 9        // 8 enc chunks + 1 location chunk

// ---- dynamic smem layout (relative to 1024-aligned base) ----
#define OFF_AH   0
#define OFF_AL   16384
#define OFF_B    32768          // two stages of (BH 16K | BL 16K)
#define BSTAGE   32768
#define OFF_QB   98304          // 128 floats
#define OFF_VV   (OFF_QB + 512)
#define OFF_PREV (OFF_VV + 512)   // 158 floats
#define OFF_PART (OFF_PREV + 640) // 2*128 floats
#define SMEM_REQ (OFF_PART + 1024 + 1024)   // + alignment slack

// ---- device scratch ----
__device__ __align__(16) float g_energy[B_ * T_];
__device__ float         g_qb[B_ * AD];
__device__ __align__(16) __nv_bfloat16 g_BT_hi[AD * ENC];
__device__ __align__(16) __nv_bfloat16 g_BT_lo[AD * ENC];
__device__ __align__(16) __nv_bfloat16 g_W2T_hi[AD * KCH];
__device__ __align__(16) __nv_bfloat16 g_W2T_lo[AD * KCH];

// ============================ helpers ============================
__device__ __forceinline__ uint32_t smem_u32(const void* p) {
    uint32_t a;
    asm("{ .reg .u64 t; cvta.to.shared.u64 t, %1; cvt.u32.u64 %0, t; }"
        : "=r"(a) : "l"(p));
    return a;
}
__device__ __forceinline__ uint32_t sw128(uint32_t off) {
    return off ^ ((off >> 3) & 0x70);
}
// pack two floats -> bf16x2 (f0 in low half)
__device__ __forceinline__ uint32_t pk(float f0, float f1) {
    uint32_t r;
    asm("cvt.rn.bf16x2.f32 %0, %1, %2;" : "=r"(r) : "f"(f1), "f"(f0));
    return r;
}
__device__ __forceinline__ void split8(const float* f, uint4& h, uint4& l) {
    float hf[8], lf[8];
    #pragma unroll
    for (int j = 0; j < 8; j++) {
        float x = f[j];
        float hv = __bfloat162float(__float2bfloat16_rn(x));
        hf[j] = hv;
        lf[j] = x - hv;
    }
    h.x = pk(hf[0], hf[1]); h.y = pk(hf[2], hf[3]);
    h.z = pk(hf[4], hf[5]); h.w = pk(hf[6], hf[7]);
    l.x = pk(lf[0], lf[1]); l.y = pk(lf[2], lf[3]);
    l.z = pk(lf[4], lf[5]); l.w = pk(lf[6], lf[7]);
}
#define LDSM4(r0, r1, r2, r3, addr)                                            \
    asm volatile("ldmatrix.sync.aligned.m8n8.x4.shared.b16 {%0,%1,%2,%3}, [%4];" \
                 : "=r"(r0), "=r"(r1), "=r"(r2), "=r"(r3) : "r"(addr))
#define MMA(c, a, b0, b1)                                                      \
    asm volatile("mma.sync.aligned.m16n8k16.row.col.f32.bf16.bf16.f32 "        \
                 "{%0,%1,%2,%3}, {%4,%5,%6,%7}, {%8,%9}, {%0,%1,%2,%3};"       \
                 : "+f"((c)[0]), "+f"((c)[1]), "+f"((c)[2]), "+f"((c)[3])      \
                 : "r"((a)[0]), "r"((a)[1]), "r"((a)[2]), "r"((a)[3]),         \
                   "r"(b0), "r"(b1))
#define CPASYNC16(dst, src)                                                    \
    asm volatile("cp.async.cg.shared.global [%0], [%1], 16;"                   \
                 :: "r"(dst), "l"(src))
#define CPCOMMIT() asm volatile("cp.async.commit_group;" ::: "memory")
#define CPWAIT1()  asm volatile("cp.async.wait_group 1;" ::: "memory")
#define CPWAIT0()  asm volatile("cp.async.wait_group 0;" ::: "memory")

// ---- stage A(chunk cc) fp32 into regs (no lambda: free function) ----
__device__ __forceinline__ void stage_A_fn(float stA[4][8], int cc, int tid,
                                           const float* __restrict__ encb,
                                           const float* __restrict__ pv_s) {
    if (cc < 8) {
        const float* src = encb + cc * KCH;
        #pragma unroll
        for (int i = 0; i < 4; i++) {
            int idx = tid + i * 256;
            int row = idx >> 3, g = idx & 7;
            float4 f0 = *(const float4*)(src + (size_t)row * ENC + g * 8);
            float4 f1 = *(const float4*)(src + (size_t)row * ENC + g * 8 + 4);
            stA[i][0]=f0.x; stA[i][1]=f0.y; stA[i][2]=f0.z; stA[i][3]=f0.w;
            stA[i][4]=f1.x; stA[i][5]=f1.y; stA[i][6]=f1.z; stA[i][7]=f1.w;
        }
    } else {
        #pragma unroll
        for (int i = 0; i < 4; i++) {
            int idx = tid + i * 256;
            int row = idx >> 3, g = idx & 7;
            #pragma unroll
            for (int j = 0; j < 8; j++) {
                int k = g * 8 + j;
                stA[i][j] = (k < KS) ? pv_s[row + k] : 0.f;
            }
        }
    }
}
// ---- issue cp.async for B(chunk cc) into its stage buffer ----
__device__ __forceinline__ void fill_B_fn(int cc, int tid, uint32_t base) {
    const __nv_bfloat16* bh_src = (cc < 8) ? g_BT_hi : g_W2T_hi;
    const __nv_bfloat16* bl_src = (cc < 8) ? g_BT_lo : g_W2T_lo;
    const int stride = (cc < 8) ? ENC : KCH;
    const int coff   = (cc < 8) ? cc * KCH : 0;
    const uint32_t sb = base + OFF_B + (uint32_t)(cc & 1) * BSTAGE;
    #pragma unroll
    for (int i = 0; i < 4; i++) {
        int idx = tid + i * 256;
        int n = idx >> 3, g = idx & 7;
        uint32_t off = sw128((uint32_t)(n * 128 + g * 16));
        CPASYNC16(sb + off,         bh_src + (size_t)n * stride + coff + g * 8);
        CPASYNC16(sb + 16384 + off, bl_src + (size_t)n * stride + coff + g * 8);
    }
}

// ============================ prep kernels ============================
__global__ void prep_bt_kernel(const float* __restrict__ Wk) {
    int n = blockIdx.x;           // 0..127
    int k = threadIdx.x;          // 0..511
    float x = Wk[(size_t)k * AD + n];
    float hv = __bfloat162float(__float2bfloat16_rn(x));
    g_BT_hi[n * ENC + k] = __float2bfloat16_rn(x);
    g_BT_lo[n * ENC + k] = __float2bfloat16_rn(x - hv);
}
__global__ void prep_w2t_kernel(const float* __restrict__ conv_w,
                                const float* __restrict__ Wl) {
    int k = blockIdx.x;           // 0..63
    int n = threadIdx.x;          // 0..127
    float w = 0.f;
    if (k < KS) {
        #pragma unroll
        for (int c = 0; c < CH; c++)
            w += conv_w[c * KS + k] * Wl[c * AD + n];
    }
    float hv = __bfloat162float(__float2bfloat16_rn(w));
    g_W2T_hi[n * KCH + k] = __float2bfloat16_rn(w);
    g_W2T_lo[n * KCH + k] = __float2bfloat16_rn(w - hv);
}
__global__ void prep_qb_kernel(const float* __restrict__ dec,
                               const float* __restrict__ Wq,
                               const float* __restrict__ conv_b,
                               const float* __restrict__ Wl) {
    int b = blockIdx.x, a = threadIdx.x;
    float s = 0.f;
    #pragma unroll 8
    for (int q = 0; q < QD; q++)
        s += dec[b * QD + q] * Wq[q * AD + a];
    #pragma unroll
    for (int c = 0; c < CH; c++)
        s += conv_b[c] * Wl[c * AD + a];
    g_qb[b * AD + a] = s;
}

// ============================ energy kernel ============================
// CTA: 128 t-rows x 128 attn dims; 8 warps (4m x 2n), warp tile 32x64.
// Pipelined: A fp32 staged in regs one chunk ahead (LDG under MMA),
// B double-buffered in smem via cp.async one chunk ahead.
__global__ __launch_bounds__(256, 2)
void energy_kernel(const float* __restrict__ enc,
                   const float* __restrict__ prev,
                   const float* __restrict__ v) {
    extern __shared__ char smraw[];
    const uint32_t raw = smem_u32(smraw);
    const uint32_t base = (raw + 1023u) & ~1023u;
    char* sm = smraw + (base - raw);

    const int b    = blockIdx.y;
    const int t0   = blockIdx.x * MT;
    const int tid  = threadIdx.x;
    const int lane = tid & 31;
    const int wid  = tid >> 5;
    const int warp_m  = (wid & 3) * 32;
    const int warp_n2 = (wid >> 2) * 64;

    float* qb_s = (float*)(sm + OFF_QB);
    float* vv_s = (float*)(sm + OFF_VV);
    float* pv_s = (float*)(sm + OFF_PREV);
    float* part = (float*)(sm + OFF_PART);

    if (tid < AD) {
        qb_s[tid] = g_qb[b * AD + tid];
        vv_s[tid] = v[tid];
    }
    for (int i = tid; i < MT + KS - 1; i += 256) {
        int tg = t0 + i - PADK;
        pv_s[i] = (tg >= 0 && tg < T_) ? prev[b * T_ + tg] : 0.f;
    }
    __syncthreads();   // pv_s ready; qb/vv for epilogue

    float acc[2][8][4];
    #pragma unroll
    for (int mt = 0; mt < 2; mt++)
        #pragma unroll
        for (int j = 0; j < 8; j++)
            #pragma unroll
            for (int r = 0; r < 4; r++) acc[mt][j][r] = 0.f;

    const float* encb = enc + ((size_t)b * T_ + t0) * ENC;
    float stA[4][8];                    // staged fp32 A for next chunk

    // prologue
    stage_A_fn(stA, 0, tid, encb, pv_s);
    fill_B_fn(0, tid, base); CPCOMMIT();

    for (int c = 0; c < NCHUNK; c++) {
        __syncthreads();   // prev MMA done with A smem and bbuf[(c+1)&1]
        // ---- STS A(c): convert staged fp32 -> bf16 hi/lo smem ----
        #pragma unroll
        for (int i = 0; i < 4; i++) {
            int idx = tid + i * 256;
            int row = idx >> 3, g = idx & 7;
            uint4 h, l; split8(stA[i], h, l);
            uint32_t off = sw128((uint32_t)(row * 128 + g * 16));
            *(uint4*)(sm + OFF_AH + off) = h;
            *(uint4*)(sm + OFF_AL + off) = l;
        }
        if (c < 8) {
            fill_B_fn(c + 1, tid, base); CPCOMMIT();
            stage_A_fn(stA, c + 1, tid, encb, pv_s);  // LDG hides under MMA
            CPWAIT1();                 // B(c) complete
        } else {
            CPWAIT0();
        }
        __syncthreads();

        const uint32_t bb = base + OFF_B + (uint32_t)(c & 1) * BSTAGE;
        // ---- mma over this chunk: 4 k16 steps ----
        #pragma unroll
        for (int kk = 0; kk < 4; kk++) {
            const uint32_t kb = (uint32_t)(kk * 32) + ((lane >> 4) & 1) * 16;
            uint32_t ah[2][4], al[2][4];
            #pragma unroll
            for (int mt = 0; mt < 2; mt++) {
                int row = warp_m + mt * 16 + (lane & 15);
                uint32_t off = sw128((uint32_t)(row * 128) + kb);
                LDSM4(ah[mt][0], ah[mt][1], ah[mt][2], ah[mt][3],
                      base + OFF_AH + off);
                LDSM4(al[mt][0], al[mt][1], al[mt][2], al[mt][3],
                      base + OFF_AL + off);
            }
            #pragma unroll
            for (int h = 0; h < 2; h++) {
                const uint32_t kbb = (uint32_t)(kk * 32) + ((lane >> 3) & 1) * 16;
                uint32_t bh[2][4], bl[2][4];
                #pragma unroll
                for (int q = 0; q < 2; q++) {
                    int n = warp_n2 + h * 32 + q * 16
                          + ((lane >> 4) << 3) + (lane & 7);
                    uint32_t off = sw128((uint32_t)(n * 128) + kbb);
                    LDSM4(bh[q][0], bh[q][1], bh[q][2], bh[q][3], bb + off);
                    LDSM4(bl[q][0], bl[q][1], bl[q][2], bl[q][3],
                          bb + 16384 + off);
                }
                #pragma unroll
                for (int mt = 0; mt < 2; mt++) {
                    #pragma unroll
                    for (int q = 0; q < 2; q++) {
                        int j = h * 4 + q * 2;
                        MMA(acc[mt][j],     ah[mt], bh[q][0], bh[q][1]);
                        MMA(acc[mt][j + 1], ah[mt], bh[q][2], bh[q][3]);
                        MMA(acc[mt][j],     ah[mt], bl[q][0], bl[q][1]);
                        MMA(acc[mt][j + 1], ah[mt], bl[q][2], bl[q][3]);
                        MMA(acc[mt][j],     al[mt], bh[q][0], bh[q][1]);
                        MMA(acc[mt][j + 1], al[mt], bh[q][2], bh[q][3]);
                    }
                }
            }
        }
    }

    // ---- epilogue: tanh + dot(v) + reduce ----
    float pr[4] = {0.f, 0.f, 0.f, 0.f};
    #pragma unroll
    for (int mt = 0; mt < 2; mt++) {
        #pragma unroll
        for (int j = 0; j < 8; j++) {
            int n0 = warp_n2 + j * 8 + 2 * (lane & 3);
            float v0 = vv_s[n0], v1 = vv_s[n0 + 1];
            float q0 = qb_s[n0], q1 = qb_s[n0 + 1];
            #pragma unroll
            for (int rh = 0; rh < 2; rh++) {
                float x0 = acc[mt][j][rh * 2]     + q0;
                float x1 = acc[mt][j][rh * 2 + 1] + q1;
                x0 = fminf(fmaxf(x0, -15.f), 15.f);
                x1 = fminf(fmaxf(x1, -15.f), 15.f);
                float e0 = __expf(2.f * x0), e1 = __expf(2.f * x1);
                float th0 = (e0 - 1.f) * __frcp_rn(e0 + 1.f);
                float th1 = (e1 - 1.f) * __frcp_rn(e1 + 1.f);
                pr[mt * 2 + rh] += th0 * v0 + th1 * v1;
            }
        }
    }
    #pragma unroll
    for (int i = 0; i < 4; i++) {
        pr[i] += __shfl_xor_sync(0xffffffffu, pr[i], 1);
        pr[i] += __shfl_xor_sync(0xffffffffu, pr[i], 2);
    }
    const int wn = wid >> 2;
    if ((lane & 3) == 0) {
        int rbase = warp_m + (lane >> 2);
        part[wn * 128 + rbase]      = pr[0];
        part[wn * 128 + rbase + 8]  = pr[1];
        part[wn * 128 + rbase + 16] = pr[2];
        part[wn * 128 + rbase + 24] = pr[3];
    }
    __syncthreads();
    if (tid < MT)
        g_energy[b * T_ + t0 + tid] = part[tid] + part[128 + tid];
}

// ============================ softmax ============================
__global__ __launch_bounds__(512)
void softmax_kernel(float* __restrict__ out) {
    __shared__ float red[16];
    const int b = blockIdx.x, tid = threadIdx.x;
    const int lane = tid & 31, warp = tid >> 5;
    const float4* e4 = (const float4*)(g_energy + b * T_);
    float4 f = e4[tid];

    float mx = fmaxf(fmaxf(f.x, f.y), fmaxf(f.z, f.w));
    #pragma unroll
    for (int o = 16; o; o >>= 1)
        mx = fmaxf(mx, __shfl_xor_sync(0xffffffffu, mx, o));
    if (lane == 0) red[warp] = mx;
    __syncthreads();
    mx = red[lane & 15];
    #pragma unroll
    for (int o = 8; o; o >>= 1)
        mx = fmaxf(mx, __shfl_xor_sync(0xffffffffu, mx, o));

    float4 ex;
    ex.x = __expf(f.x - mx); ex.y = __expf(f.y - mx);
    ex.z = __expf(f.z - mx); ex.w = __expf(f.w - mx);
    float sum = ex.x + ex.y + ex.z + ex.w;
    #pragma unroll
    for (int o = 16; o; o >>= 1)
        sum += __shfl_xor_sync(0xffffffffu, sum, o);
    __syncthreads();
    if (lane == 0) red[warp] = sum;
    __syncthreads();
    sum = red[lane & 15];
    #pragma unroll
    for (int o = 8; o; o >>= 1)
        sum += __shfl_xor_sync(0xffffffffu, sum, o);
    float inv = 1.f / sum;

    float4 o4; o4.x = ex.x*inv; o4.y = ex.y*inv; o4.z = ex.z*inv; o4.w = ex.w*inv;
    ((float4*)(out + b * T_))[tid] = o4;
}

// ============================ launch ============================
extern "C" void kernel_launch(void* const* d_in, const int* in_sizes, int n_in,
                              void* d_out, int out_size) {
    const float* enc    = (const float*)d_in[0];
    const float* dec    = (const float*)d_in[1];
    const float* prev   = (const float*)d_in[2];
    const float* Wq     = (const float*)d_in[3];
    const float* Wk     = (const float*)d_in[4];
    const float* conv_w = (const float*)d_in[5];
    const float* conv_b = (const float*)d_in[6];
    const float* Wl     = (const float*)d_in[7];
    const float* v      = (const float*)d_in[8];
    float* out = (float*)d_out;

    cudaFuncSetAttribute(energy_kernel,
                         cudaFuncAttributeMaxDynamicSharedMemorySize, SMEM_REQ);

    prep_bt_kernel<<<AD, ENC>>>(Wk);
    prep_w2t_kernel<<<KCH, AD>>>(conv_w, Wl);
    prep_qb_kernel<<<B_, AD>>>(dec, Wq, conv_b, Wl);
    energy_kernel<<<dim3(T_ / MT, B_), 256, SMEM_REQ>>>(enc, prev, v);
    softmax_kernel<<<B_, 512>>>(out);
}

// round 8
// speedup vs baseline: 2.1543x; 1.0452x over previous
#include <cuda_runtime.h>
#include <cuda_bf16.h>
#include <cstdint>
#include <math.h>

#define B_    64
#define T_    2048
#define ENC   512
#define QD    256
#define AD    128
#define CH    32
#define KS    31
#define PADK  15

#define MT     128      // t-rows per CTA
#define KCH    64       // k per chunk (64 bf16 = 128B rows, SW128)
#define NCHUNK 9        // 8 enc chunks + 1 location chunk

// ---- dynamic smem layout (relative to 1024-aligned base) ----
#define OFF_AH   0
#define OFF_AL   16384
#define OFF_B    32768          // two stages of (BH 16K | BL 16K)
#define BSTAGE   32768
#define OFF_QB   98304          // 128 floats
#define OFF_VV   (OFF_QB + 512)
#define OFF_PREV (OFF_VV + 512)   // 158 floats
#define OFF_PART (OFF_PREV + 640) // 2*128 floats
#define SMEM_REQ (OFF_PART + 1024 + 1024)   // + alignment slack

// ---- device scratch ----
__device__ __align__(16) float g_energy[B_ * T_];
__device__ float         g_qb[B_ * AD];
__device__ __align__(16) __nv_bfloat16 g_BT_hi[AD * ENC];
__device__ __align__(16) __nv_bfloat16 g_BT_lo[AD * ENC];
__device__ __align__(16) __nv_bfloat16 g_W2T_hi[AD * KCH];
__device__ __align__(16) __nv_bfloat16 g_W2T_lo[AD * KCH];

// ============================ helpers ============================
__device__ __forceinline__ uint32_t smem_u32(const void* p) {
    uint32_t a;
    asm("{ .reg .u64 t; cvta.to.shared.u64 t, %1; cvt.u32.u64 %0, t; }"
        : "=r"(a) : "l"(p));
    return a;
}
__device__ __forceinline__ uint32_t sw128(uint32_t off) {
    return off ^ ((off >> 3) & 0x70);
}
// pack two floats -> bf16x2 (f0 in low half)
__device__ __forceinline__ uint32_t pk(float f0, float f1) {
    uint32_t r;
    asm("cvt.rn.bf16x2.f32 %0, %1, %2;" : "=r"(r) : "f"(f1), "f"(f0));
    return r;
}
__device__ __forceinline__ void split8(const float* f, uint4& h, uint4& l) {
    float hf[8], lf[8];
    #pragma unroll
    for (int j = 0; j < 8; j++) {
        float x = f[j];
        float hv = __bfloat162float(__float2bfloat16_rn(x));
        hf[j] = hv;
        lf[j] = x - hv;
    }
    h.x = pk(hf[0], hf[1]); h.y = pk(hf[2], hf[3]);
    h.z = pk(hf[4], hf[5]); h.w = pk(hf[6], hf[7]);
    l.x = pk(lf[0], lf[1]); l.y = pk(lf[2], lf[3]);
    l.z = pk(lf[4], lf[5]); l.w = pk(lf[6], lf[7]);
}
#define LDSM4(r0, r1, r2, r3, addr)                                            \
    asm volatile("ldmatrix.sync.aligned.m8n8.x4.shared.b16 {%0,%1,%2,%3}, [%4];" \
                 : "=r"(r0), "=r"(r1), "=r"(r2), "=r"(r3) : "r"(addr))
#define MMA(c, a, b0, b1)                                                      \
    asm volatile("mma.sync.aligned.m16n8k16.row.col.f32.bf16.bf16.f32 "        \
                 "{%0,%1,%2,%3}, {%4,%5,%6,%7}, {%8,%9}, {%0,%1,%2,%3};"       \
                 : "+f"((c)[0]), "+f"((c)[1]), "+f"((c)[2]), "+f"((c)[3])      \
                 : "r"((a)[0]), "r"((a)[1]), "r"((a)[2]), "r"((a)[3]),         \
                   "r"(b0), "r"(b1))
#define CPASYNC16(dst, src)                                                    \
    asm volatile("cp.async.cg.shared.global [%0], [%1], 16;"                   \
                 :: "r"(dst), "l"(src))
#define CPCOMMIT() asm volatile("cp.async.commit_group;" ::: "memory")
#define CPWAIT1()  asm volatile("cp.async.wait_group 1;" ::: "memory")
#define CPWAIT0()  asm volatile("cp.async.wait_group 0;" ::: "memory")

// ---- stage A(chunk cc) fp32 into regs. Loads are asm volatile so ptxas
// cannot hoist them above the (volatile) MMA asm of the current chunk:
// stA's live range must not overlap the fragment registers. ----
__device__ __forceinline__ void stage_A_fn(float stA[4][8], int cc, int tid,
                                           const float* __restrict__ encb,
                                           const float* __restrict__ pv_s) {
    if (cc < 8) {
        const float* src = encb + cc * KCH;
        #pragma unroll
        for (int i = 0; i < 4; i++) {
            int idx = tid + i * 256;
            int row = idx >> 3, g = idx & 7;
            const float* p = src + (size_t)row * ENC + g * 8;
            asm volatile("ld.global.nc.v4.f32 {%0,%1,%2,%3}, [%4];"
                : "=f"(stA[i][0]), "=f"(stA[i][1]),
                  "=f"(stA[i][2]), "=f"(stA[i][3]) : "l"(p));
            asm volatile("ld.global.nc.v4.f32 {%0,%1,%2,%3}, [%4];"
                : "=f"(stA[i][4]), "=f"(stA[i][5]),
                  "=f"(stA[i][6]), "=f"(stA[i][7]) : "l"(p + 4));
        }
    } else {
        #pragma unroll
        for (int i = 0; i < 4; i++) {
            int idx = tid + i * 256;
            int row = idx >> 3, g = idx & 7;
            #pragma unroll
            for (int j = 0; j < 8; j++) {
                int k = g * 8 + j;
                stA[i][j] = (k < KS) ? pv_s[row + k] : 0.f;
            }
        }
    }
}
// ---- issue cp.async for B(chunk cc) into its stage buffer ----
__device__ __forceinline__ void fill_B_fn(int cc, int tid, uint32_t base) {
    const __nv_bfloat16* bh_src = (cc < 8) ? g_BT_hi : g_W2T_hi;
    const __nv_bfloat16* bl_src = (cc < 8) ? g_BT_lo : g_W2T_lo;
    const int stride = (cc < 8) ? ENC : KCH;
    const int coff   = (cc < 8) ? cc * KCH : 0;
    const uint32_t sb = base + OFF_B + (uint32_t)(cc & 1) * BSTAGE;
    #pragma unroll
    for (int i = 0; i < 4; i++) {
        int idx = tid + i * 256;
        int n = idx >> 3, g = idx & 7;
        uint32_t off = sw128((uint32_t)(n * 128 + g * 16));
        CPASYNC16(sb + off,         bh_src + (size_t)n * stride + coff + g * 8);
        CPASYNC16(sb + 16384 + off, bl_src + (size_t)n * stride + coff + g * 8);
    }
}

// ============================ prep kernels ============================
__global__ void prep_bt_kernel(const float* __restrict__ Wk) {
    int n = blockIdx.x;           // 0..127
    int k = threadIdx.x;          // 0..511
    float x = Wk[(size_t)k * AD + n];
    float hv = __bfloat162float(__float2bfloat16_rn(x));
    g_BT_hi[n * ENC + k] = __float2bfloat16_rn(x);
    g_BT_lo[n * ENC + k] = __float2bfloat16_rn(x - hv);
}
__global__ void prep_w2t_kernel(const float* __restrict__ conv_w,
                                const float* __restrict__ Wl) {
    int k = blockIdx.x;           // 0..63
    int n = threadIdx.x;          // 0..127
    float w = 0.f;
    if (k < KS) {
        #pragma unroll
        for (int c = 0; c < CH; c++)
            w += conv_w[c * KS + k] * Wl[c * AD + n];
    }
    float hv = __bfloat162float(__float2bfloat16_rn(w));
    g_W2T_hi[n * KCH + k] = __float2bfloat16_rn(w);
    g_W2T_lo[n * KCH + k] = __float2bfloat16_rn(w - hv);
}
__global__ void prep_qb_kernel(const float* __restrict__ dec,
                               const float* __restrict__ Wq,
                               const float* __restrict__ conv_b,
                               const float* __restrict__ Wl) {
    int b = blockIdx.x, a = threadIdx.x;
    float s = 0.f;
    #pragma unroll 8
    for (int q = 0; q < QD; q++)
        s += dec[b * QD + q] * Wq[q * AD + a];
    #pragma unroll
    for (int c = 0; c < CH; c++)
        s += conv_b[c] * Wl[c * AD + a];
    g_qb[b * AD + a] = s;
}

// ============================ energy kernel ============================
// CTA: 128 t-rows x 128 attn dims; 8 warps (4m x 2n), warp tile 32x64.
// Pipelined: A fp32 staged in regs one chunk ahead (LDG sunk below MMAs so
// stA never coexists with fragments -> no spills),
// B double-buffered in smem via cp.async one chunk ahead.
__global__ __launch_bounds__(256, 2)
void energy_kernel(const float* __restrict__ enc,
                   const float* __restrict__ prev,
                   const float* __restrict__ v) {
    extern __shared__ char smraw[];
    const uint32_t raw = smem_u32(smraw);
    const uint32_t base = (raw + 1023u) & ~1023u;
    char* sm = smraw + (base - raw);

    const int b    = blockIdx.y;
    const int t0   = blockIdx.x * MT;
    const int tid  = threadIdx.x;
    const int lane = tid & 31;
    const int wid  = tid >> 5;
    const int warp_m  = (wid & 3) * 32;
    const int warp_n2 = (wid >> 2) * 64;

    float* qb_s = (float*)(sm + OFF_QB);
    float* vv_s = (float*)(sm + OFF_VV);
    float* pv_s = (float*)(sm + OFF_PREV);
    float* part = (float*)(sm + OFF_PART);

    if (tid < AD) {
        qb_s[tid] = g_qb[b * AD + tid];
        vv_s[tid] = v[tid];
    }
    for (int i = tid; i < MT + KS - 1; i += 256) {
        int tg = t0 + i - PADK;
        pv_s[i] = (tg >= 0 && tg < T_) ? prev[b * T_ + tg] : 0.f;
    }
    __syncthreads();   // pv_s ready; qb/vv for epilogue

    float acc[2][8][4];
    #pragma unroll
    for (int mt = 0; mt < 2; mt++)
        #pragma unroll
        for (int j = 0; j < 8; j++)
            #pragma unroll
            for (int r = 0; r < 4; r++) acc[mt][j][r] = 0.f;

    const float* encb = enc + ((size_t)b * T_ + t0) * ENC;
    float stA[4][8];                    // staged fp32 A for next chunk

    // prologue
    stage_A_fn(stA, 0, tid, encb, pv_s);
    fill_B_fn(0, tid, base); CPCOMMIT();

    for (int c = 0; c < NCHUNK; c++) {
        __syncthreads();   // prev MMA done with A smem and bbuf[(c+1)&1]
        // ---- STS A(c): convert staged fp32 -> bf16 hi/lo smem ----
        #pragma unroll
        for (int i = 0; i < 4; i++) {
            int idx = tid + i * 256;
            int row = idx >> 3, g = idx & 7;
            uint4 h, l; split8(stA[i], h, l);
            uint32_t off = sw128((uint32_t)(row * 128 + g * 16));
            *(uint4*)(sm + OFF_AH + off) = h;
            *(uint4*)(sm + OFF_AL + off) = l;
        }
        if (c < 8) {
            fill_B_fn(c + 1, tid, base); CPCOMMIT();
            CPWAIT1();                 // B(c) complete
        } else {
            CPWAIT0();
        }
        __syncthreads();

        const uint32_t bb = base + OFF_B + (uint32_t)(c & 1) * BSTAGE;
        // ---- mma over this chunk: 4 k16 steps ----
        // All 12 LDSM4 of a kk-step are issued BEFORE its 48 MMAs: full MLP
        // on the fragment loads, one LDS->HMMA wait per kk instead of per-h.
        #pragma unroll
        for (int kk = 0; kk < 4; kk++) {
            const uint32_t kb  = (uint32_t)(kk * 32) + ((lane >> 4) & 1) * 16;
            const uint32_t kbb = (uint32_t)(kk * 32) + ((lane >> 3) & 1) * 16;
            uint32_t ah[2][4], al[2][4];
            uint32_t bh[4][4], bl[4][4];   // 4 q-tiles across both h halves
            #pragma unroll
            for (int mt = 0; mt < 2; mt++) {
                int row = warp_m + mt * 16 + (lane & 15);
                uint32_t off = sw128((uint32_t)(row * 128) + kb);
                LDSM4(ah[mt][0], ah[mt][1], ah[mt][2], ah[mt][3],
                      base + OFF_AH + off);
                LDSM4(al[mt][0], al[mt][1], al[mt][2], al[mt][3],
                      base + OFF_AL + off);
            }
            #pragma unroll
            for (int hq = 0; hq < 4; hq++) {      // hq = h*2 + q
                int n = warp_n2 + (hq >> 1) * 32 + (hq & 1) * 16
                      + ((lane >> 4) << 3) + (lane & 7);
                uint32_t off = sw128((uint32_t)(n * 128) + kbb);
                LDSM4(bh[hq][0], bh[hq][1], bh[hq][2], bh[hq][3], bb + off);
                LDSM4(bl[hq][0], bl[hq][1], bl[hq][2], bl[hq][3],
                      bb + 16384 + off);
            }
            #pragma unroll
            for (int mt = 0; mt < 2; mt++) {
                #pragma unroll
                for (int hq = 0; hq < 4; hq++) {
                    int j = hq * 2;
                    MMA(acc[mt][j],     ah[mt], bh[hq][0], bh[hq][1]);
                    MMA(acc[mt][j + 1], ah[mt], bh[hq][2], bh[hq][3]);
                    MMA(acc[mt][j],     ah[mt], bl[hq][0], bl[hq][1]);
                    MMA(acc[mt][j + 1], ah[mt], bl[hq][2], bl[hq][3]);
                    MMA(acc[mt][j],     al[mt], bh[hq][0], bh[hq][1]);
                    MMA(acc[mt][j + 1], al[mt], bh[hq][2], bh[hq][3]);
                }
            }
        }

        // ---- stage A(c+1) AFTER the MMAs (volatile loads stay sunk) ----
        if (c < 8)
            stage_A_fn(stA, c + 1, tid, encb, pv_s);
    }

    // ---- epilogue: tanh + dot(v) + reduce ----
    float pr[4] = {0.f, 0.f, 0.f, 0.f};
    #pragma unroll
    for (int mt = 0; mt < 2; mt++) {
        #pragma unroll
        for (int j = 0; j < 8; j++) {
            int n0 = warp_n2 + j * 8 + 2 * (lane & 3);
            float v0 = vv_s[n0], v1 = vv_s[n0 + 1];
            float q0 = qb_s[n0], q1 = qb_s[n0 + 1];
            #pragma unroll
            for (int rh = 0; rh < 2; rh++) {
                float x0 = acc[mt][j][rh * 2]     + q0;
                float x1 = acc[mt][j][rh * 2 + 1] + q1;
                x0 = fminf(fmaxf(x0, -15.f), 15.f);
                x1 = fminf(fmaxf(x1, -15.f), 15.f);
                float e0 = __expf(2.f * x0), e1 = __expf(2.f * x1);
                float th0 = (e0 - 1.f) * __frcp_rn(e0 + 1.f);
                float th1 = (e1 - 1.f) * __frcp_rn(e1 + 1.f);
                pr[mt * 2 + rh] += th0 * v0 + th1 * v1;
            }
        }
    }
    #pragma unroll
    for (int i = 0; i < 4; i++) {
        pr[i] += __shfl_xor_sync(0xffffffffu, pr[i], 1);
        pr[i] += __shfl_xor_sync(0xffffffffu, pr[i], 2);
    }
    const int wn = wid >> 2;
    if ((lane & 3) == 0) {
        int rbase = warp_m + (lane >> 2);
        part[wn * 128 + rbase]      = pr[0];
        part[wn * 128 + rbase + 8]  = pr[1];
        part[wn * 128 + rbase + 16] = pr[2];
        part[wn * 128 + rbase + 24] = pr[3];
    }
    __syncthreads();
    if (tid < MT)
        g_energy[b * T_ + t0 + tid] = part[tid] + part[128 + tid];
}

// ============================ softmax ============================
__global__ __launch_bounds__(512)
void softmax_kernel(float* __restrict__ out) {
    __shared__ float red[16];
    const int b = blockIdx.x, tid = threadIdx.x;
    const int lane = tid & 31, warp = tid >> 5;
    const float4* e4 = (const float4*)(g_energy + b * T_);
    float4 f = e4[tid];

    float mx = fmaxf(fmaxf(f.x, f.y), fmaxf(f.z, f.w));
    #pragma unroll
    for (int o = 16; o; o >>= 1)
        mx = fmaxf(mx, __shfl_xor_sync(0xffffffffu, mx, o));
    if (lane == 0) red[warp] = mx;
    __syncthreads();
    mx = red[lane & 15];
    #pragma unroll
    for (int o = 8; o; o >>= 1)
        mx = fmaxf(mx, __shfl_xor_sync(0xffffffffu, mx, o));

    float4 ex;
    ex.x = __expf(f.x - mx); ex.y = __expf(f.y - mx);
    ex.z = __expf(f.z - mx); ex.w = __expf(f.w - mx);
    float sum = ex.x + ex.y + ex.z + ex.w;
    #pragma unroll
    for (int o = 16; o; o >>= 1)
        sum += __shfl_xor_sync(0xffffffffu, sum, o);
    __syncthreads();
    if (lane == 0) red[warp] = sum;
    __syncthreads();
    sum = red[lane & 15];
    #pragma unroll
    for (int o = 8; o; o >>= 1)
        sum += __shfl_xor_sync(0xffffffffu, sum, o);
    float inv = 1.f / sum;

    float4 o4; o4.x = ex.x*inv; o4.y = ex.y*inv; o4.z = ex.z*inv; o4.w = ex.w*inv;
    ((float4*)(out + b * T_))[tid] = o4;
}

// ============================ launch ============================
extern "C" void kernel_launch(void* const* d_in, const int* in_sizes, int n_in,
                              void* d_out, int out_size) {
    const float* enc    = (const float*)d_in[0];
    const float* dec    = (const float*)d_in[1];
    const float* prev   = (const float*)d_in[2];
    const float* Wq     = (const float*)d_in[3];
    const float* Wk     = (const float*)d_in[4];
    const float* conv_w = (const float*)d_in[5];
    const float* conv_b = (const float*)d_in[6];
    const float* Wl     = (const float*)d_in[7];
    const float* v      = (const float*)d_in[8];
    float* out = (float*)d_out;

    cudaFuncSetAttribute(energy_kernel,
                         cudaFuncAttributeMaxDynamicSharedMemorySize, SMEM_REQ);

    prep_bt_kernel<<<AD, ENC>>>(Wk);
    prep_w2t_kernel<<<KCH, AD>>>(conv_w, Wl);
    prep_qb_kernel<<<B_, AD>>>(dec, Wq, conv_b, Wl);
    energy_kernel<<<dim3(T_ / MT, B_), 256, SMEM_REQ>>>(enc, prev, v);
    softmax_kernel<<<B_, 512>>>(out);
}

// round 10
// speedup vs baseline: 2.7681x; 1.2849x over previous
#include <cuda_runtime.h>
#include <cuda_fp16.h>
#include <cstdint>
#include <math.h>

#define B_    64
#define T_    2048
#define ENC   512
#define QD    256
#define AD    128
#define CH    32
#define KS    31
#define PADK  15

#define MT     128      // t-rows per CTA
#define KCH    64       // k per chunk (64 fp16 = 128B rows, SW128)
#define NCHUNK 9        // 8 enc chunks + 1 location chunk

// ---- dynamic smem layout (relative to 1024-aligned base) ----
#define OFF_AH   0              // 128x64 fp16 = 16 KB
#define OFF_AL   16384
#define OFF_B    32768          // two stages of 16 KB (B single fp16)
#define BSTAGE   16384
#define OFF_QB   65536          // 128 floats
#define OFF_VV   (OFF_QB + 512)
#define OFF_PREV (OFF_VV + 512)   // 158 floats
#define OFF_PART (OFF_PREV + 640) // 2*128 floats
#define SMEM_REQ (OFF_PART + 1024 + 1024)   // + alignment slack

// ---- device scratch ----
__device__ __align__(16) float g_energy[B_ * T_];
__device__ float         g_qb[B_ * AD];
__device__ __align__(16) __half g_BT[AD * ENC];      // Wk^T, K-major fp16
__device__ __align__(16) __half g_W2T[AD * KCH];     // W2^T fp16

// ============================ helpers ============================
__device__ __forceinline__ uint32_t smem_u32(const void* p) {
    uint32_t a;
    asm("{ .reg .u64 t; cvta.to.shared.u64 t, %1; cvt.u32.u64 %0, t; }"
        : "=r"(a) : "l"(p));
    return a;
}
__device__ __forceinline__ uint32_t sw128(uint32_t off) {
    return off ^ ((off >> 3) & 0x70);
}
// pack two floats -> f16x2 (f0 in low half)
__device__ __forceinline__ uint32_t pkh(float f0, float f1) {
    uint32_t r;
    asm("cvt.rn.f16x2.f32 %0, %1, %2;" : "=r"(r) : "f"(f1), "f"(f0));
    return r;
}
// split 8 floats into hi/lo fp16 uint4s (A 2-term split)
__device__ __forceinline__ void split8h(const float* f, uint4& h, uint4& l) {
    float hf[8], lf[8];
    #pragma unroll
    for (int j = 0; j < 8; j++) {
        float x = f[j];
        float hv = __half2float(__float2half_rn(x));
        hf[j] = hv;
        lf[j] = x - hv;
    }
    h.x = pkh(hf[0], hf[1]); h.y = pkh(hf[2], hf[3]);
    h.z = pkh(hf[4], hf[5]); h.w = pkh(hf[6], hf[7]);
    l.x = pkh(lf[0], lf[1]); l.y = pkh(lf[2], lf[3]);
    l.z = pkh(lf[4], lf[5]); l.w = pkh(lf[6], lf[7]);
}
#define LDSM4(r0, r1, r2, r3, addr)                                            \
    asm volatile("ldmatrix.sync.aligned.m8n8.x4.shared.b16 {%0,%1,%2,%3}, [%4];" \
                 : "=r"(r0), "=r"(r1), "=r"(r2), "=r"(r3) : "r"(addr))
#define MMAH(c, a, b0, b1)                                                     \
    asm volatile("mma.sync.aligned.m16n8k16.row.col.f32.f16.f16.f32 "          \
                 "{%0,%1,%2,%3}, {%4,%5,%6,%7}, {%8,%9}, {%0,%1,%2,%3};"       \
                 : "+f"((c)[0]), "+f"((c)[1]), "+f"((c)[2]), "+f"((c)[3])      \
                 : "r"((a)[0]), "r"((a)[1]), "r"((a)[2]), "r"((a)[3]),         \
                   "r"(b0), "r"(b1))
#define CPASYNC16(dst, src)                                                    \
    asm volatile("cp.async.cg.shared.global [%0], [%1], 16;"                   \
                 :: "r"(dst), "l"(src))
#define CPCOMMIT() asm volatile("cp.async.commit_group;" ::: "memory")
#define CPWAIT1()  asm volatile("cp.async.wait_group 1;" ::: "memory")
#define CPWAIT0()  asm volatile("cp.async.wait_group 0;" ::: "memory")

// ---- stage A(chunk cc) fp32 into regs (volatile -> stays sunk below MMAs) ----
__device__ __forceinline__ void stage_A_fn(float stA[4][8], int cc, int tid,
                                           const float* __restrict__ encb,
                                           const float* __restrict__ pv_s) {
    if (cc < 8) {
        const float* src = encb + cc * KCH;
        #pragma unroll
        for (int i = 0; i < 4; i++) {
            int idx = tid + i * 256;
            int row = idx >> 3, g = idx & 7;
            const float* p = src + (size_t)row * ENC + g * 8;
            asm volatile("ld.global.nc.v4.f32 {%0,%1,%2,%3}, [%4];"
                : "=f"(stA[i][0]), "=f"(stA[i][1]),
                  "=f"(stA[i][2]), "=f"(stA[i][3]) : "l"(p));
            asm volatile("ld.global.nc.v4.f32 {%0,%1,%2,%3}, [%4];"
                : "=f"(stA[i][4]), "=f"(stA[i][5]),
                  "=f"(stA[i][6]), "=f"(stA[i][7]) : "l"(p + 4));
        }
    } else {
        #pragma unroll
        for (int i = 0; i < 4; i++) {
            int idx = tid + i * 256;
            int row = idx >> 3, g = idx & 7;
            #pragma unroll
            for (int j = 0; j < 8; j++) {
                int k = g * 8 + j;
                stA[i][j] = (k < KS) ? pv_s[row + k] : 0.f;
            }
        }
    }
}
// ---- issue cp.async for B(chunk cc): 128 n x 64 k fp16, single term ----
__device__ __forceinline__ void fill_B_fn(int cc, int tid, uint32_t base) {
    const __half* bsrc = (cc < 8) ? g_BT : g_W2T;
    const int stride = (cc < 8) ? ENC : KCH;
    const int coff   = (cc < 8) ? cc * KCH : 0;
    const uint32_t sb = base + OFF_B + (uint32_t)(cc & 1) * BSTAGE;
    #pragma unroll
    for (int i = 0; i < 4; i++) {
        int idx = tid + i * 256;
        int n = idx >> 3, g = idx & 7;
        uint32_t off = sw128((uint32_t)(n * 128 + g * 16));
        CPASYNC16(sb + off, bsrc + (size_t)n * stride + coff + g * 8);
    }
}

// ============================ prep kernels ============================
__global__ void prep_bt_kernel(const float* __restrict__ Wk) {
    int n = blockIdx.x;           // 0..127
    int k = threadIdx.x;          // 0..511
    g_BT[n * ENC + k] = __float2half_rn(Wk[(size_t)k * AD + n]);
}
__global__ void prep_w2t_kernel(const float* __restrict__ conv_w,
                                const float* __restrict__ Wl) {
    int k = blockIdx.x;           // 0..63
    int n = threadIdx.x;          // 0..127
    float w = 0.f;
    if (k < KS) {
        #pragma unroll
        for (int c = 0; c < CH; c++)
            w += conv_w[c * KS + k] * Wl[c * AD + n];
    }
    g_W2T[n * KCH + k] = __float2half_rn(w);
}
__global__ void prep_qb_kernel(const float* __restrict__ dec,
                               const float* __restrict__ Wq,
                               const float* __restrict__ conv_b,
                               const float* __restrict__ Wl) {
    int b = blockIdx.x, a = threadIdx.x;
    float s = 0.f;
    #pragma unroll 8
    for (int q = 0; q < QD; q++)
        s += dec[b * QD + q] * Wq[q * AD + a];
    #pragma unroll
    for (int c = 0; c < CH; c++)
        s += conv_b[c] * Wl[c * AD + a];
    g_qb[b * AD + a] = s;
}

// ============================ energy kernel ============================
// CTA: 128 t-rows x 128 attn dims; 8 warps (4m x 2n), warp tile 32x64.
// fp16 2-term: D = Ah*B + Al*B (B single fp16; A split hi/lo).
// A fp32 staged in regs one chunk ahead; B double-buffered via cp.async.
__global__ __launch_bounds__(256, 2)
void energy_kernel(const float* __restrict__ enc,
                   const float* __restrict__ prev,
                   const float* __restrict__ v) {
    extern __shared__ char smraw[];
    const uint32_t raw = smem_u32(smraw);
    const uint32_t base = (raw + 1023u) & ~1023u;
    char* sm = smraw + (base - raw);

    const int b    = blockIdx.y;
    const int t0   = blockIdx.x * MT;
    const int tid  = threadIdx.x;
    const int lane = tid & 31;
    const int wid  = tid >> 5;
    const int warp_m  = (wid & 3) * 32;
    const int warp_n2 = (wid >> 2) * 64;

    float* qb_s = (float*)(sm + OFF_QB);
    float* vv_s = (float*)(sm + OFF_VV);
    float* pv_s = (float*)(sm + OFF_PREV);
    float* part = (float*)(sm + OFF_PART);

    if (tid < AD) {
        qb_s[tid] = g_qb[b * AD + tid];
        vv_s[tid] = v[tid];
    }
    for (int i = tid; i < MT + KS - 1; i += 256) {
        int tg = t0 + i - PADK;
        pv_s[i] = (tg >= 0 && tg < T_) ? prev[b * T_ + tg] : 0.f;
    }
    __syncthreads();   // pv_s ready; qb/vv for epilogue

    float acc[2][8][4];
    #pragma unroll
    for (int mt = 0; mt < 2; mt++)
        #pragma unroll
        for (int j = 0; j < 8; j++)
            #pragma unroll
            for (int r = 0; r < 4; r++) acc[mt][j][r] = 0.f;

    const float* encb = enc + ((size_t)b * T_ + t0) * ENC;
    float stA[4][8];                    // staged fp32 A for next chunk

    // prologue
    stage_A_fn(stA, 0, tid, encb, pv_s);
    fill_B_fn(0, tid, base); CPCOMMIT();

    for (int c = 0; c < NCHUNK; c++) {
        __syncthreads();   // prev MMA done with A smem and bbuf[(c+1)&1]
        // ---- STS A(c): convert staged fp32 -> fp16 hi/lo smem ----
        #pragma unroll
        for (int i = 0; i < 4; i++) {
            int idx = tid + i * 256;
            int row = idx >> 3, g = idx & 7;
            uint4 h, l; split8h(stA[i], h, l);
            uint32_t off = sw128((uint32_t)(row * 128 + g * 16));
            *(uint4*)(sm + OFF_AH + off) = h;
            *(uint4*)(sm + OFF_AL + off) = l;
        }
        if (c < 8) {
            fill_B_fn(c + 1, tid, base); CPCOMMIT();
            CPWAIT1();                 // B(c) complete
        } else {
            CPWAIT0();
        }
        __syncthreads();

        const uint32_t bb = base + OFF_B + (uint32_t)(c & 1) * BSTAGE;
        // ---- mma over this chunk: 4 k16 steps; 8 LDSM + 32 MMA per kk ----
        #pragma unroll
        for (int kk = 0; kk < 4; kk++) {
            const uint32_t kb  = (uint32_t)(kk * 32) + ((lane >> 4) & 1) * 16;
            const uint32_t kbb = (uint32_t)(kk * 32) + ((lane >> 3) & 1) * 16;
            uint32_t ah[2][4], al[2][4];
            uint32_t bf[4][4];             // 4 q-tiles across both n halves
            #pragma unroll
            for (int mt = 0; mt < 2; mt++) {
                int row = warp_m + mt * 16 + (lane & 15);
                uint32_t off = sw128((uint32_t)(row * 128) + kb);
                LDSM4(ah[mt][0], ah[mt][1], ah[mt][2], ah[mt][3],
                      base + OFF_AH + off);
                LDSM4(al[mt][0], al[mt][1], al[mt][2], al[mt][3],
                      base + OFF_AL + off);
            }
            #pragma unroll
            for (int hq = 0; hq < 4; hq++) {      // hq = h*2 + q
                int n = warp_n2 + (hq >> 1) * 32 + (hq & 1) * 16
                      + ((lane >> 4) << 3) + (lane & 7);
                uint32_t off = sw128((uint32_t)(n * 128) + kbb);
                LDSM4(bf[hq][0], bf[hq][1], bf[hq][2], bf[hq][3], bb + off);
            }
            #pragma unroll
            for (int mt = 0; mt < 2; mt++) {
                #pragma unroll
                for (int hq = 0; hq < 4; hq++) {
                    int j = hq * 2;
                    MMAH(acc[mt][j],     ah[mt], bf[hq][0], bf[hq][1]);
                    MMAH(acc[mt][j + 1], ah[mt], bf[hq][2], bf[hq][3]);
                    MMAH(acc[mt][j],     al[mt], bf[hq][0], bf[hq][1]);
                    MMAH(acc[mt][j + 1], al[mt], bf[hq][2], bf[hq][3]);
                }
            }
        }

        // ---- stage A(c+1) AFTER the MMAs (volatile loads stay sunk) ----
        if (c < 8)
            stage_A_fn(stA, c + 1, tid, encb, pv_s);
    }

    // ---- epilogue: tanh + dot(v) + reduce ----
    float pr[4] = {0.f, 0.f, 0.f, 0.f};
    #pragma unroll
    for (int mt = 0; mt < 2; mt++) {
        #pragma unroll
        for (int j = 0; j < 8; j++) {
            int n0 = warp_n2 + j * 8 + 2 * (lane & 3);
            float v0 = vv_s[n0], v1 = vv_s[n0 + 1];
            float q0 = qb_s[n0], q1 = qb_s[n0 + 1];
            #pragma unroll
            for (int rh = 0; rh < 2; rh++) {
                float x0 = acc[mt][j][rh * 2]     + q0;
                float x1 = acc[mt][j][rh * 2 + 1] + q1;
                x0 = fminf(fmaxf(x0, -15.f), 15.f);
                x1 = fminf(fmaxf(x1, -15.f), 15.f);
                float e0 = __expf(2.f * x0), e1 = __expf(2.f * x1);
                float th0 = (e0 - 1.f) * __frcp_rn(e0 + 1.f);
                float th1 = (e1 - 1.f) * __frcp_rn(e1 + 1.f);
                pr[mt * 2 + rh] += th0 * v0 + th1 * v1;
            }
        }
    }
    #pragma unroll
    for (int i = 0; i < 4; i++) {
        pr[i] += __shfl_xor_sync(0xffffffffu, pr[i], 1);
        pr[i] += __shfl_xor_sync(0xffffffffu, pr[i], 2);
    }
    const int wn = wid >> 2;
    if ((lane & 3) == 0) {
        int rbase = warp_m + (lane >> 2);
        part[wn * 128 + rbase]      = pr[0];
        part[wn * 128 + rbase + 8]  = pr[1];
        part[wn * 128 + rbase + 16] = pr[2];
        part[wn * 128 + rbase + 24] = pr[3];
    }
    __syncthreads();
    if (tid < MT)
        g_energy[b * T_ + t0 + tid] = part[tid] + part[128 + tid];
}

// ============================ softmax ============================
__global__ __launch_bounds__(512)
void softmax_kernel(float* __restrict__ out) {
    __shared__ float red[16];
    const int b = blockIdx.x, tid = threadIdx.x;
    const int lane = tid & 31, warp = tid >> 5;
    const float4* e4 = (const float4*)(g_energy + b * T_);
    float4 f = e4[tid];

    float mx = fmaxf(fmaxf(f.x, f.y), fmaxf(f.z, f.w));
    #pragma unroll
    for (int o = 16; o; o >>= 1)
        mx = fmaxf(mx, __shfl_xor_sync(0xffffffffu, mx, o));
    if (lane == 0) red[warp] = mx;
    __syncthreads();
    mx = red[lane & 15];
    #pragma unroll
    for (int o = 8; o; o >>= 1)
        mx = fmaxf(mx, __shfl_xor_sync(0xffffffffu, mx, o));

    float4 ex;
    ex.x = __expf(f.x - mx); ex.y = __expf(f.y - mx);
    ex.z = __expf(f.z - mx); ex.w = __expf(f.w - mx);
    float sum = ex.x + ex.y + ex.z + ex.w;
    #pragma unroll
    for (int o = 16; o; o >>= 1)
        sum += __shfl_xor_sync(0xffffffffu, sum, o);
    __syncthreads();
    if (lane == 0) red[warp] = sum;
    __syncthreads();
    sum = red[lane & 15];
    #pragma unroll
    for (int o = 8; o; o >>= 1)
        sum += __shfl_xor_sync(0xffffffffu, sum, o);
    float inv = 1.f / sum;

    float4 o4; o4.x = ex.x*inv; o4.y = ex.y*inv; o4.z = ex.z*inv; o4.w = ex.w*inv;
    ((float4*)(out + b * T_))[tid] = o4;
}

// ============================ launch ============================
extern "C" void kernel_launch(void* const* d_in, const int* in_sizes, int n_in,
                              void* d_out, int out_size) {
    const float* enc    = (const float*)d_in[0];
    const float* dec    = (const float*)d_in[1];
    const float* prev   = (const float*)d_in[2];
    const float* Wq     = (const float*)d_in[3];
    const float* Wk     = (const float*)d_in[4];
    const float* conv_w = (const float*)d_in[5];
    const float* conv_b = (const float*)d_in[6];
    const float* Wl     = (const float*)d_in[7];
    const float* v      = (const float*)d_in[8];
    float* out = (float*)d_out;

    cudaFuncSetAttribute(energy_kernel,
                         cudaFuncAttributeMaxDynamicSharedMemorySize, SMEM_REQ);

    prep_bt_kernel<<<AD, ENC>>>(Wk);
    prep_w2t_kernel<<<KCH, AD>>>(conv_w, Wl);
    prep_qb_kernel<<<B_, AD>>>(dec, Wq, conv_b, Wl);
    energy_kernel<<<dim3(T_ / MT, B_), 256, SMEM_REQ>>>(enc, prev, v);
    softmax_kernel<<<B_, 512>>>(out);
}

// round 11
// speedup vs baseline: 3.3638x; 1.2152x over previous
#include <cuda_runtime.h>
#include <cuda_fp16.h>
#include <cstdint>
#include <math.h>

#define B_    64
#define T_    2048
#define ENC   512
#define QD    256
#define AD    128
#define CH    32
#define KS    31
#define PADK  15

#define MT     128      // t-rows per CTA
#define KCH    64       // k per chunk (64 fp16 = 128B rows, SW128)
#define NCHUNK 9        // 8 enc chunks + 1 location chunk

// ---- dynamic smem layout (relative to 1024-aligned base) ----
#define OFF_A    0              // 128x64 fp16 = 16 KB (single term)
#define OFF_B    16384          // two stages of 16 KB (B single fp16)
#define BSTAGE   16384
#define OFF_QB   49152          // 128 floats
#define OFF_VV   (OFF_QB + 512)
#define OFF_PREV (OFF_VV + 512)   // 158 floats
#define OFF_PART (OFF_PREV + 640) // 2*128 floats
#define SMEM_REQ (OFF_PART + 1024 + 1024)   // + alignment slack

// ---- device scratch ----
__device__ __align__(16) float g_energy[B_ * T_];
__device__ float         g_qb[B_ * AD];
__device__ __align__(16) __half g_BT[AD * ENC];      // Wk^T, K-major fp16
__device__ __align__(16) __half g_W2T[AD * KCH];     // W2^T fp16

// ============================ helpers ============================
__device__ __forceinline__ uint32_t smem_u32(const void* p) {
    uint32_t a;
    asm("{ .reg .u64 t; cvta.to.shared.u64 t, %1; cvt.u32.u64 %0, t; }"
        : "=r"(a) : "l"(p));
    return a;
}
__device__ __forceinline__ uint32_t sw128(uint32_t off) {
    return off ^ ((off >> 3) & 0x70);
}
// pack two floats -> f16x2 (f0 in low half)
__device__ __forceinline__ uint32_t pkh(float f0, float f1) {
    uint32_t r;
    asm("cvt.rn.f16x2.f32 %0, %1, %2;" : "=r"(r) : "f"(f1), "f"(f0));
    return r;
}
// convert 8 floats -> fp16 uint4 (single term)
__device__ __forceinline__ void cvt8h(const float* f, uint4& h) {
    h.x = pkh(f[0], f[1]); h.y = pkh(f[2], f[3]);
    h.z = pkh(f[4], f[5]); h.w = pkh(f[6], f[7]);
}
#define LDSM4(r0, r1, r2, r3, addr)                                            \
    asm volatile("ldmatrix.sync.aligned.m8n8.x4.shared.b16 {%0,%1,%2,%3}, [%4];" \
                 : "=r"(r0), "=r"(r1), "=r"(r2), "=r"(r3) : "r"(addr))
#define MMAH(c, a, b0, b1)                                                     \
    asm volatile("mma.sync.aligned.m16n8k16.row.col.f32.f16.f16.f32 "          \
                 "{%0,%1,%2,%3}, {%4,%5,%6,%7}, {%8,%9}, {%0,%1,%2,%3};"       \
                 : "+f"((c)[0]), "+f"((c)[1]), "+f"((c)[2]), "+f"((c)[3])      \
                 : "r"((a)[0]), "r"((a)[1]), "r"((a)[2]), "r"((a)[3]),         \
                   "r"(b0), "r"(b1))
#define CPASYNC16(dst, src)                                                    \
    asm volatile("cp.async.cg.shared.global [%0], [%1], 16;"                   \
                 :: "r"(dst), "l"(src))
#define CPCOMMIT() asm volatile("cp.async.commit_group;" ::: "memory")
#define CPWAIT1()  asm volatile("cp.async.wait_group 1;" ::: "memory")
#define CPWAIT0()  asm volatile("cp.async.wait_group 0;" ::: "memory")

// ---- stage A(chunk cc) fp32 into regs (volatile -> stays sunk below MMAs) ----
__device__ __forceinline__ void stage_A_fn(float stA[4][8], int cc, int tid,
                                           const float* __restrict__ encb,
                                           const float* __restrict__ pv_s) {
    if (cc < 8) {
        const float* src = encb + cc * KCH;
        #pragma unroll
        for (int i = 0; i < 4; i++) {
            int idx = tid + i * 256;
            int row = idx >> 3, g = idx & 7;
            const float* p = src + (size_t)row * ENC + g * 8;
            asm volatile("ld.global.nc.v4.f32 {%0,%1,%2,%3}, [%4];"
                : "=f"(stA[i][0]), "=f"(stA[i][1]),
                  "=f"(stA[i][2]), "=f"(stA[i][3]) : "l"(p));
            asm volatile("ld.global.nc.v4.f32 {%0,%1,%2,%3}, [%4];"
                : "=f"(stA[i][4]), "=f"(stA[i][5]),
                  "=f"(stA[i][6]), "=f"(stA[i][7]) : "l"(p + 4));
        }
    } else {
        #pragma unroll
        for (int i = 0; i < 4; i++) {
            int idx = tid + i * 256;
            int row = idx >> 3, g = idx & 7;
            #pragma unroll
            for (int j = 0; j < 8; j++) {
                int k = g * 8 + j;
                stA[i][j] = (k < KS) ? pv_s[row + k] : 0.f;
            }
        }
    }
}
// ---- issue cp.async for B(chunk cc): 128 n x 64 k fp16, single term ----
__device__ __forceinline__ void fill_B_fn(int cc, int tid, uint32_t base) {
    const __half* bsrc = (cc < 8) ? g_BT : g_W2T;
    const int stride = (cc < 8) ? ENC : KCH;
    const int coff   = (cc < 8) ? cc * KCH : 0;
    const uint32_t sb = base + OFF_B + (uint32_t)(cc & 1) * BSTAGE;
    #pragma unroll
    for (int i = 0; i < 4; i++) {
        int idx = tid + i * 256;
        int n = idx >> 3, g = idx & 7;
        uint32_t off = sw128((uint32_t)(n * 128 + g * 16));
        CPASYNC16(sb + off, bsrc + (size_t)n * stride + coff + g * 8);
    }
}

// ============================ prep kernels ============================
__global__ void prep_bt_kernel(const float* __restrict__ Wk) {
    int n = blockIdx.x;           // 0..127
    int k = threadIdx.x;          // 0..511
    g_BT[n * ENC + k] = __float2half_rn(Wk[(size_t)k * AD + n]);
}
__global__ void prep_w2t_kernel(const float* __restrict__ conv_w,
                                const float* __restrict__ Wl) {
    int k = blockIdx.x;           // 0..63
    int n = threadIdx.x;          // 0..127
    float w = 0.f;
    if (k < KS) {
        #pragma unroll
        for (int c = 0; c < CH; c++)
            w += conv_w[c * KS + k] * Wl[c * AD + n];
    }
    g_W2T[n * KCH + k] = __float2half_rn(w);
}
__global__ void prep_qb_kernel(const float* __restrict__ dec,
                               const float* __restrict__ Wq,
                               const float* __restrict__ conv_b,
                               const float* __restrict__ Wl) {
    int b = blockIdx.x, a = threadIdx.x;
    float s = 0.f;
    #pragma unroll 8
    for (int q = 0; q < QD; q++)
        s += dec[b * QD + q] * Wq[q * AD + a];
    #pragma unroll
    for (int c = 0; c < CH; c++)
        s += conv_b[c] * Wl[c * AD + a];
    g_qb[b * AD + a] = s;
}

// ============================ energy kernel ============================
// CTA: 128 t-rows x 128 attn dims; 8 warps (4m x 2n), warp tile 32x64.
// Single-term fp16: D = A*B (both fp16-rounded; error ~3e-4 << 1e-3).
// A fp32 staged in regs one chunk ahead; B double-buffered via cp.async.
__global__ __launch_bounds__(256, 2)
void energy_kernel(const float* __restrict__ enc,
                   const float* __restrict__ prev,
                   const float* __restrict__ v) {
    extern __shared__ char smraw[];
    const uint32_t raw = smem_u32(smraw);
    const uint32_t base = (raw + 1023u) & ~1023u;
    char* sm = smraw + (base - raw);

    const int b    = blockIdx.y;
    const int t0   = blockIdx.x * MT;
    const int tid  = threadIdx.x;
    const int lane = tid & 31;
    const int wid  = tid >> 5;
    const int warp_m  = (wid & 3) * 32;
    const int warp_n2 = (wid >> 2) * 64;

    float* qb_s = (float*)(sm + OFF_QB);
    float* vv_s = (float*)(sm + OFF_VV);
    float* pv_s = (float*)(sm + OFF_PREV);
    float* part = (float*)(sm + OFF_PART);

    if (tid < AD) {
        qb_s[tid] = g_qb[b * AD + tid];
        vv_s[tid] = v[tid];
    }
    for (int i = tid; i < MT + KS - 1; i += 256) {
        int tg = t0 + i - PADK;
        pv_s[i] = (tg >= 0 && tg < T_) ? prev[b * T_ + tg] : 0.f;
    }
    __syncthreads();   // pv_s ready; qb/vv for epilogue

    float acc[2][8][4];
    #pragma unroll
    for (int mt = 0; mt < 2; mt++)
        #pragma unroll
        for (int j = 0; j < 8; j++)
            #pragma unroll
            for (int r = 0; r < 4; r++) acc[mt][j][r] = 0.f;

    const float* encb = enc + ((size_t)b * T_ + t0) * ENC;
    float stA[4][8];                    // staged fp32 A for next chunk

    // prologue
    stage_A_fn(stA, 0, tid, encb, pv_s);
    fill_B_fn(0, tid, base); CPCOMMIT();

    for (int c = 0; c < NCHUNK; c++) {
        __syncthreads();   // prev MMA done with A smem and bbuf[(c+1)&1]
        // ---- STS A(c): convert staged fp32 -> fp16 smem ----
        #pragma unroll
        for (int i = 0; i < 4; i++) {
            int idx = tid + i * 256;
            int row = idx >> 3, g = idx & 7;
            uint4 h; cvt8h(stA[i], h);
            uint32_t off = sw128((uint32_t)(row * 128 + g * 16));
            *(uint4*)(sm + OFF_A + off) = h;
        }
        if (c < 8) {
            fill_B_fn(c + 1, tid, base); CPCOMMIT();
            CPWAIT1();                 // B(c) complete
        } else {
            CPWAIT0();
        }
        __syncthreads();

        const uint32_t bb = base + OFF_B + (uint32_t)(c & 1) * BSTAGE;
        // ---- mma over this chunk: 4 k16 steps; 6 LDSM + 16 MMA per kk ----
        #pragma unroll
        for (int kk = 0; kk < 4; kk++) {
            const uint32_t kb  = (uint32_t)(kk * 32) + ((lane >> 4) & 1) * 16;
            const uint32_t kbb = (uint32_t)(kk * 32) + ((lane >> 3) & 1) * 16;
            uint32_t ah[2][4];
            uint32_t bf[4][4];             // 4 q-tiles across both n halves
            #pragma unroll
            for (int mt = 0; mt < 2; mt++) {
                int row = warp_m + mt * 16 + (lane & 15);
                uint32_t off = sw128((uint32_t)(row * 128) + kb);
                LDSM4(ah[mt][0], ah[mt][1], ah[mt][2], ah[mt][3],
                      base + OFF_A + off);
            }
            #pragma unroll
            for (int hq = 0; hq < 4; hq++) {      // hq = h*2 + q
                int n = warp_n2 + (hq >> 1) * 32 + (hq & 1) * 16
                      + ((lane >> 4) << 3) + (lane & 7);
                uint32_t off = sw128((uint32_t)(n * 128) + kbb);
                LDSM4(bf[hq][0], bf[hq][1], bf[hq][2], bf[hq][3], bb + off);
            }
            #pragma unroll
            for (int mt = 0; mt < 2; mt++) {
                #pragma unroll
                for (int hq = 0; hq < 4; hq++) {
                    int j = hq * 2;
                    MMAH(acc[mt][j],     ah[mt], bf[hq][0], bf[hq][1]);
                    MMAH(acc[mt][j + 1], ah[mt], bf[hq][2], bf[hq][3]);
                }
            }
        }

        // ---- stage A(c+1) AFTER the MMAs (volatile loads stay sunk) ----
        if (c < 8)
            stage_A_fn(stA, c + 1, tid, encb, pv_s);
    }

    // ---- epilogue: tanh + dot(v) + reduce ----
    float pr[4] = {0.f, 0.f, 0.f, 0.f};
    #pragma unroll
    for (int mt = 0; mt < 2; mt++) {
        #pragma unroll
        for (int j = 0; j < 8; j++) {
            int n0 = warp_n2 + j * 8 + 2 * (lane & 3);
            float v0 = vv_s[n0], v1 = vv_s[n0 + 1];
            float q0 = qb_s[n0], q1 = qb_s[n0 + 1];
            #pragma unroll
            for (int rh = 0; rh < 2; rh++) {
                float x0 = acc[mt][j][rh * 2]     + q0;
                float x1 = acc[mt][j][rh * 2 + 1] + q1;
                x0 = fminf(fmaxf(x0, -15.f), 15.f);
                x1 = fminf(fmaxf(x1, -15.f), 15.f);
                float e0 = __expf(2.f * x0), e1 = __expf(2.f * x1);
                float th0 = (e0 - 1.f) * __frcp_rn(e0 + 1.f);
                float th1 = (e1 - 1.f) * __frcp_rn(e1 + 1.f);
                pr[mt * 2 + rh] += th0 * v0 + th1 * v1;
            }
        }
    }
    #pragma unroll
    for (int i = 0; i < 4; i++) {
        pr[i] += __shfl_xor_sync(0xffffffffu, pr[i], 1);
        pr[i] += __shfl_xor_sync(0xffffffffu, pr[i], 2);
    }
    const int wn = wid >> 2;
    if ((lane & 3) == 0) {
        int rbase = warp_m + (lane >> 2);
        part[wn * 128 + rbase]      = pr[0];
        part[wn * 128 + rbase + 8]  = pr[1];
        part[wn * 128 + rbase + 16] = pr[2];
        part[wn * 128 + rbase + 24] = pr[3];
    }
    __syncthreads();
    if (tid < MT)
        g_energy[b * T_ + t0 + tid] = part[tid] + part[128 + tid];
}

// ============================ softmax ============================
__global__ __launch_bounds__(512)
void softmax_kernel(float* __restrict__ out) {
    __shared__ float red[16];
    const int b = blockIdx.x, tid = threadIdx.x;
    const int lane = tid & 31, warp = tid >> 5;
    const float4* e4 = (const float4*)(g_energy + b * T_);
    float4 f = e4[tid];

    float mx = fmaxf(fmaxf(f.x, f.y), fmaxf(f.z, f.w));
    #pragma unroll
    for (int o = 16; o; o >>= 1)
        mx = fmaxf(mx, __shfl_xor_sync(0xffffffffu, mx, o));
    if (lane == 0) red[warp] = mx;
    __syncthreads();
    mx = red[lane & 15];
    #pragma unroll
    for (int o = 8; o; o >>= 1)
        mx = fmaxf(mx, __shfl_xor_sync(0xffffffffu, mx, o));

    float4 ex;
    ex.x = __expf(f.x - mx); ex.y = __expf(f.y - mx);
    ex.z = __expf(f.z - mx); ex.w = __expf(f.w - mx);
    float sum = ex.x + ex.y + ex.z + ex.w;
    #pragma unroll
    for (int o = 16; o; o >>= 1)
        sum += __shfl_xor_sync(0xffffffffu, sum, o);
    __syncthreads();
    if (lane == 0) red[warp] = sum;
    __syncthreads();
    sum = red[lane & 15];
    #pragma unroll
    for (int o = 8; o; o >>= 1)
        sum += __shfl_xor_sync(0xffffffffu, sum, o);
    float inv = 1.f / sum;

    float4 o4; o4.x = ex.x*inv; o4.y = ex.y*inv; o4.z = ex.z*inv; o4.w = ex.w*inv;
    ((float4*)(out + b * T_))[tid] = o4;
}

// ============================ launch ============================
extern "C" void kernel_launch(void* const* d_in, const int* in_sizes, int n_in,
                              void* d_out, int out_size) {
    const float* enc    = (const float*)d_in[0];
    const float* dec    = (const float*)d_in[1];
    const float* prev   = (const float*)d_in[2];
    const float* Wq     = (const float*)d_in[3];
    const float* Wk     = (const float*)d_in[4];
    const float* conv_w = (const float*)d_in[5];
    const float* conv_b = (const float*)d_in[6];
    const float* Wl     = (const float*)d_in[7];
    const float* v      = (const float*)d_in[8];
    float* out = (float*)d_out;

    cudaFuncSetAttribute(energy_kernel,
                         cudaFuncAttributeMaxDynamicSharedMemorySize, SMEM_REQ);

    prep_bt_kernel<<<AD, ENC>>>(Wk);
    prep_w2t_kernel<<<KCH, AD>>>(conv_w, Wl);
    prep_qb_kernel<<<B_, AD>>>(dec, Wq, conv_b, Wl);
    energy_kernel<<<dim3(T_ / MT, B_), 256, SMEM_REQ>>>(enc, prev, v);
    softmax_kernel<<<B_, 512>>>(out);
}

// round 12
// speedup vs baseline: 3.6784x; 1.0935x over previous
#include <cuda_runtime.h>
#include <cuda_fp16.h>
#include <cstdint>
#include <math.h>

#define B_    64
#define T_    2048
#define ENC   512
#define QD    256
#define AD    128
#define CH    32
#define KS    31
#define PADK  15

#define MT     64       // t-rows per CTA (halved: 3 CTAs/SM)
#define KCH    64       // k per chunk (64 fp16 = 128B rows, SW128)
#define NCHUNK 9        // 8 enc chunks + 1 location chunk

// ---- dynamic smem layout (relative to 1024-aligned base) ----
#define OFF_A    0              // 64x64 fp16 = 8 KB (single term)
#define OFF_B    8192           // two stages of 16 KB (B single fp16)
#define BSTAGE   16384
#define OFF_QB   40960          // 128 floats
#define OFF_VV   (OFF_QB + 512)
#define OFF_PREV (OFF_VV + 512)   // 94 floats (pad 384)
#define OFF_PART (OFF_PREV + 384) // 4*64 floats = 1024B
#define SMEM_REQ (OFF_PART + 1024 + 2048)   // + alignment slack

// ---- device scratch ----
__device__ __align__(16) float g_energy[B_ * T_];
__device__ float         g_qb[B_ * AD];
__device__ __align__(16) __half g_BT[AD * ENC];      // Wk^T, K-major fp16
__device__ __align__(16) __half g_W2T[AD * KCH];     // W2^T fp16

// ============================ helpers ============================
__device__ __forceinline__ uint32_t smem_u32(const void* p) {
    uint32_t a;
    asm("{ .reg .u64 t; cvta.to.shared.u64 t, %1; cvt.u32.u64 %0, t; }"
        : "=r"(a) : "l"(p));
    return a;
}
__device__ __forceinline__ uint32_t sw128(uint32_t off) {
    return off ^ ((off >> 3) & 0x70);
}
// pack two floats -> f16x2 (f0 in low half)
__device__ __forceinline__ uint32_t pkh(float f0, float f1) {
    uint32_t r;
    asm("cvt.rn.f16x2.f32 %0, %1, %2;" : "=r"(r) : "f"(f1), "f"(f0));
    return r;
}
// convert 8 floats -> fp16 uint4 (single term)
__device__ __forceinline__ void cvt8h(const float* f, uint4& h) {
    h.x = pkh(f[0], f[1]); h.y = pkh(f[2], f[3]);
    h.z = pkh(f[4], f[5]); h.w = pkh(f[6], f[7]);
}
#define LDSM4(r0, r1, r2, r3, addr)                                            \
    asm volatile("ldmatrix.sync.aligned.m8n8.x4.shared.b16 {%0,%1,%2,%3}, [%4];" \
                 : "=r"(r0), "=r"(r1), "=r"(r2), "=r"(r3) : "r"(addr))
#define MMAH(c, a, b0, b1)                                                     \
    asm volatile("mma.sync.aligned.m16n8k16.row.col.f32.f16.f16.f32 "          \
                 "{%0,%1,%2,%3}, {%4,%5,%6,%7}, {%8,%9}, {%0,%1,%2,%3};"       \
                 : "+f"((c)[0]), "+f"((c)[1]), "+f"((c)[2]), "+f"((c)[3])      \
                 : "r"((a)[0]), "r"((a)[1]), "r"((a)[2]), "r"((a)[3]),         \
                   "r"(b0), "r"(b1))
#define CPASYNC16(dst, src)                                                    \
    asm volatile("cp.async.cg.shared.global [%0], [%1], 16;"                   \
                 :: "r"(dst), "l"(src))
#define CPCOMMIT() asm volatile("cp.async.commit_group;" ::: "memory")
#define CPWAIT1()  asm volatile("cp.async.wait_group 1;" ::: "memory")
#define CPWAIT0()  asm volatile("cp.async.wait_group 0;" ::: "memory")

// ---- stage A(chunk cc) fp32 into regs: 64 rows x 64 k, 16 floats/thread ----
__device__ __forceinline__ void stage_A_fn(float stA[2][8], int cc, int tid,
                                           const float* __restrict__ encb,
                                           const float* __restrict__ pv_s) {
    if (cc < 8) {
        const float* src = encb + cc * KCH;
        #pragma unroll
        for (int i = 0; i < 2; i++) {
            int idx = tid + i * 256;
            int row = idx >> 3, g = idx & 7;
            const float* p = src + (size_t)row * ENC + g * 8;
            asm volatile("ld.global.nc.v4.f32 {%0,%1,%2,%3}, [%4];"
                : "=f"(stA[i][0]), "=f"(stA[i][1]),
                  "=f"(stA[i][2]), "=f"(stA[i][3]) : "l"(p));
            asm volatile("ld.global.nc.v4.f32 {%0,%1,%2,%3}, [%4];"
                : "=f"(stA[i][4]), "=f"(stA[i][5]),
                  "=f"(stA[i][6]), "=f"(stA[i][7]) : "l"(p + 4));
        }
    } else {
        #pragma unroll
        for (int i = 0; i < 2; i++) {
            int idx = tid + i * 256;
            int row = idx >> 3, g = idx & 7;
            #pragma unroll
            for (int j = 0; j < 8; j++) {
                int k = g * 8 + j;
                stA[i][j] = (k < KS) ? pv_s[row + k] : 0.f;
            }
        }
    }
}
// ---- issue cp.async for B(chunk cc): 128 n x 64 k fp16 ----
__device__ __forceinline__ void fill_B_fn(int cc, int tid, uint32_t base) {
    const __half* bsrc = (cc < 8) ? g_BT : g_W2T;
    const int stride = (cc < 8) ? ENC : KCH;
    const int coff   = (cc < 8) ? cc * KCH : 0;
    const uint32_t sb = base + OFF_B + (uint32_t)(cc & 1) * BSTAGE;
    #pragma unroll
    for (int i = 0; i < 4; i++) {
        int idx = tid + i * 256;
        int n = idx >> 3, g = idx & 7;
        uint32_t off = sw128((uint32_t)(n * 128 + g * 16));
        CPASYNC16(sb + off, bsrc + (size_t)n * stride + coff + g * 8);
    }
}

// ============================ merged prep kernel ============================
// blocks [0,128): BT transpose; [128,192): W2T; [192,256): qb. 512 thr each.
__global__ void prep_all_kernel(const float* __restrict__ Wk,
                                const float* __restrict__ conv_w,
                                const float* __restrict__ Wl,
                                const float* __restrict__ dec,
                                const float* __restrict__ Wq,
                                const float* __restrict__ conv_b) {
    int bx = blockIdx.x, tid = threadIdx.x;
    if (bx < 128) {
        // BT: n = bx, k = tid (0..511)
        g_BT[bx * ENC + tid] = __float2half_rn(Wk[(size_t)tid * AD + bx]);
    } else if (bx < 192) {
        // W2T: k = bx-128 (0..63), n = tid (<128)
        if (tid < AD) {
            int k = bx - 128;
            float w = 0.f;
            if (k < KS) {
                #pragma unroll
                for (int c = 0; c < CH; c++)
                    w += conv_w[c * KS + k] * Wl[c * AD + tid];
            }
            g_W2T[tid * KCH + k] = __float2half_rn(w);
        }
    } else {
        // qb: b = bx-192, a = tid (<128)
        if (tid < AD) {
            int b = bx - 192;
            float s = 0.f;
            #pragma unroll 8
            for (int q = 0; q < QD; q++)
                s += dec[b * QD + q] * Wq[q * AD + tid];
            #pragma unroll
            for (int c = 0; c < CH; c++)
                s += conv_b[c] * Wl[c * AD + tid];
            g_qb[b * AD + tid] = s;
        }
    }
}

// ============================ energy kernel ============================
// CTA: 64 t-rows x 128 attn dims; 8 warps (2m x 4n), warp tile 32x32.
// Single-term fp16. 3 CTAs/SM for cross-CTA phase overlap.
__global__ __launch_bounds__(256, 3)
void energy_kernel(const float* __restrict__ enc,
                   const float* __restrict__ prev,
                   const float* __restrict__ v) {
    extern __shared__ char smraw[];
    const uint32_t raw = smem_u32(smraw);
    const uint32_t base = (raw + 1023u) & ~1023u;
    char* sm = smraw + (base - raw);

    const int b    = blockIdx.y;
    const int t0   = blockIdx.x * MT;
    const int tid  = threadIdx.x;
    const int lane = tid & 31;
    const int wid  = tid >> 5;
    const int warp_m = (wid >> 2) * 32;   // 2 m-tiles of 32
    const int warp_n = (wid & 3) * 32;    // 4 n-tiles of 32

    float* qb_s = (float*)(sm + OFF_QB);
    float* vv_s = (float*)(sm + OFF_VV);
    float* pv_s = (float*)(sm + OFF_PREV);
    float* part = (float*)(sm + OFF_PART);

    if (tid < AD) {
        qb_s[tid] = g_qb[b * AD + tid];
        vv_s[tid] = v[tid];
    }
    if (tid < MT + KS - 1) {
        int tg = t0 + tid - PADK;
        pv_s[tid] = (tg >= 0 && tg < T_) ? prev[b * T_ + tg] : 0.f;
    }
    __syncthreads();   // pv_s ready; qb/vv for epilogue

    float acc[2][4][4];
    #pragma unroll
    for (int mt = 0; mt < 2; mt++)
        #pragma unroll
        for (int j = 0; j < 4; j++)
            #pragma unroll
            for (int r = 0; r < 4; r++) acc[mt][j][r] = 0.f;

    const float* encb = enc + ((size_t)b * T_ + t0) * ENC;
    float stA[2][8];                    // staged fp32 A for next chunk

    // prologue
    stage_A_fn(stA, 0, tid, encb, pv_s);
    fill_B_fn(0, tid, base); CPCOMMIT();

    for (int c = 0; c < NCHUNK; c++) {
        __syncthreads();   // prev MMA done with A smem and bbuf[(c+1)&1]
        // ---- STS A(c): convert staged fp32 -> fp16 smem ----
        #pragma unroll
        for (int i = 0; i < 2; i++) {
            int idx = tid + i * 256;
            int row = idx >> 3, g = idx & 7;
            uint4 h; cvt8h(stA[i], h);
            uint32_t off = sw128((uint32_t)(row * 128 + g * 16));
            *(uint4*)(sm + OFF_A + off) = h;
        }
        if (c < 8) {
            fill_B_fn(c + 1, tid, base); CPCOMMIT();
            CPWAIT1();                 // B(c) complete
        } else {
            CPWAIT0();
        }
        __syncthreads();

        const uint32_t bb = base + OFF_B + (uint32_t)(c & 1) * BSTAGE;
        // ---- mma over this chunk: 4 k16 steps; 4 LDSM + 8 MMA per kk ----
        #pragma unroll
        for (int kk = 0; kk < 4; kk++) {
            const uint32_t kb  = (uint32_t)(kk * 32) + ((lane >> 4) & 1) * 16;
            const uint32_t kbb = (uint32_t)(kk * 32) + ((lane >> 3) & 1) * 16;
            uint32_t ah[2][4];
            uint32_t bf[2][4];             // 2 n16-tiles of the 32-wide n tile
            #pragma unroll
            for (int mt = 0; mt < 2; mt++) {
                int row = warp_m + mt * 16 + (lane & 15);
                uint32_t off = sw128((uint32_t)(row * 128) + kb);
                LDSM4(ah[mt][0], ah[mt][1], ah[mt][2], ah[mt][3],
                      base + OFF_A + off);
            }
            #pragma unroll
            for (int q = 0; q < 2; q++) {
                int n = warp_n + q * 16 + ((lane >> 4) << 3) + (lane & 7);
                uint32_t off = sw128((uint32_t)(n * 128) + kbb);
                LDSM4(bf[q][0], bf[q][1], bf[q][2], bf[q][3], bb + off);
            }
            #pragma unroll
            for (int mt = 0; mt < 2; mt++) {
                #pragma unroll
                for (int q = 0; q < 2; q++) {
                    MMAH(acc[mt][q * 2],     ah[mt], bf[q][0], bf[q][1]);
                    MMAH(acc[mt][q * 2 + 1], ah[mt], bf[q][2], bf[q][3]);
                }
            }
        }

        // ---- stage A(c+1) AFTER the MMAs (volatile loads stay sunk) ----
        if (c < 8)
            stage_A_fn(stA, c + 1, tid, encb, pv_s);
    }

    // ---- epilogue: tanh + dot(v) + reduce ----
    float pr[4] = {0.f, 0.f, 0.f, 0.f};
    #pragma unroll
    for (int mt = 0; mt < 2; mt++) {
        #pragma unroll
        for (int j = 0; j < 4; j++) {
            int n0 = warp_n + j * 8 + 2 * (lane & 3);
            float v0 = vv_s[n0], v1 = vv_s[n0 + 1];
            float q0 = qb_s[n0], q1 = qb_s[n0 + 1];
            #pragma unroll
            for (int rh = 0; rh < 2; rh++) {
                float x0 = acc[mt][j][rh * 2]     + q0;
                float x1 = acc[mt][j][rh * 2 + 1] + q1;
                x0 = fminf(fmaxf(x0, -15.f), 15.f);
                x1 = fminf(fmaxf(x1, -15.f), 15.f);
                float e0 = __expf(2.f * x0), e1 = __expf(2.f * x1);
                float th0 = (e0 - 1.f) * __frcp_rn(e0 + 1.f);
                float th1 = (e1 - 1.f) * __frcp_rn(e1 + 1.f);
                pr[mt * 2 + rh] += th0 * v0 + th1 * v1;
            }
        }
    }
    #pragma unroll
    for (int i = 0; i < 4; i++) {
        pr[i] += __shfl_xor_sync(0xffffffffu, pr[i], 1);
        pr[i] += __shfl_xor_sync(0xffffffffu, pr[i], 2);
    }
    const int wn = wid & 3;               // 4 partial columns
    if ((lane & 3) == 0) {
        int rbase = warp_m + (lane >> 2);
        part[wn * MT + rbase]      = pr[0];
        part[wn * MT + rbase + 8]  = pr[1];
        part[wn * MT + rbase + 16] = pr[2];
        part[wn * MT + rbase + 24] = pr[3];
    }
    __syncthreads();
    if (tid < MT)
        g_energy[b * T_ + t0 + tid] = part[tid] + part[MT + tid]
                                    + part[2 * MT + tid] + part[3 * MT + tid];
}

// ============================ softmax ============================
__global__ __launch_bounds__(512)
void softmax_kernel(float* __restrict__ out) {
    __shared__ float red[16];
    const int b = blockIdx.x, tid = threadIdx.x;
    const int lane = tid & 31, warp = tid >> 5;
    const float4* e4 = (const float4*)(g_energy + b * T_);
    float4 f = e4[tid];

    float mx = fmaxf(fmaxf(f.x, f.y), fmaxf(f.z, f.w));
    #pragma unroll
    for (int o = 16; o; o >>= 1)
        mx = fmaxf(mx, __shfl_xor_sync(0xffffffffu, mx, o));
    if (lane == 0) red[warp] = mx;
    __syncthreads();
    mx = red[lane & 15];
    #pragma unroll
    for (int o = 8; o; o >>= 1)
        mx = fmaxf(mx, __shfl_xor_sync(0xffffffffu, mx, o));

    float4 ex;
    ex.x = __expf(f.x - mx); ex.y = __expf(f.y - mx);
    ex.z = __expf(f.z - mx); ex.w = __expf(f.w - mx);
    float sum = ex.x + ex.y + ex.z + ex.w;
    #pragma unroll
    for (int o = 16; o; o >>= 1)
        sum += __shfl_xor_sync(0xffffffffu, sum, o);
    __syncthreads();
    if (lane == 0) red[warp] = sum;
    __syncthreads();
    sum = red[lane & 15];
    #pragma unroll
    for (int o = 8; o; o >>= 1)
        sum += __shfl_xor_sync(0xffffffffu, sum, o);
    float inv = 1.f / sum;

    float4 o4; o4.x = ex.x*inv; o4.y = ex.y*inv; o4.z = ex.z*inv; o4.w = ex.w*inv;
    ((float4*)(out + b * T_))[tid] = o4;
}

// ============================ launch ============================
extern "C" void kernel_launch(void* const* d_in, const int* in_sizes, int n_in,
                              void* d_out, int out_size) {
    const float* enc    = (const float*)d_in[0];
    const float* dec    = (const float*)d_in[1];
    const float* prev   = (const float*)d_in[2];
    const float* Wq     = (const float*)d_in[3];
    const float* Wk     = (const float*)d_in[4];
    const float* conv_w = (const float*)d_in[5];
    const float* conv_b = (const float*)d_in[6];
    const float* Wl     = (const float*)d_in[7];
    const float* v      = (const float*)d_in[8];
    float* out = (float*)d_out;

    cudaFuncSetAttribute(energy_kernel,
                         cudaFuncAttributeMaxDynamicSharedMemorySize, SMEM_REQ);

    prep_all_kernel<<<256, 512>>>(Wk, conv_w, Wl, dec, Wq, conv_b);
    energy_kernel<<<dim3(T_ / MT, B_), 256, SMEM_REQ>>>(enc, prev, v);
    softmax_kernel<<<B_, 512>>>(out);
}

// round 14
// speedup vs baseline: 4.3299x; 1.1771x over previous
#include <cuda_runtime.h>
#include <cuda_fp16.h>
#include <cstdint>
#include <math.h>

#define B_    64
#define T_    2048
#define ENC   512
#define QD    256
#define AD    128
#define CH    32
#define KS    31
#define PADK  15

#define MT     64       // t-rows per CTA (3 CTAs/SM)
#define KCH    64       // k per chunk (64 fp16 = 128B rows, SW128)
#define NCHUNK 9        // 8 enc chunks + 1 location chunk

// ---- dynamic smem layout (relative to 1024-aligned base) ----
#define OFF_A    0              // two stages of 8 KB (A single-term fp16)
#define ASTAGE   8192
#define OFF_B    16384          // THREE stages of 16 KB (B single fp16)
#define BSTAGE   16384
#define OFF_QB   65536          // 128 floats
#define OFF_VV   (OFF_QB + 512)
#define OFF_PREV (OFF_VV + 512)   // 94 floats (pad 384)
#define OFF_PART (OFF_PREV + 384) // 4*64 floats = 1024B
#define SMEM_REQ (OFF_PART + 1024 + 2048)   // + alignment slack (~69.5 KB)

// ---- device scratch ----
__device__ __align__(16) float g_energy[B_ * T_];
__device__ float         g_qb[B_ * AD];
__device__ __align__(16) __half g_BT[AD * ENC];      // Wk^T, K-major fp16
__device__ __align__(16) __half g_W2T[AD * KCH];     // W2^T fp16

// ============================ helpers ============================
__device__ __forceinline__ uint32_t smem_u32(const void* p) {
    uint32_t a;
    asm("{ .reg .u64 t; cvta.to.shared.u64 t, %1; cvt.u32.u64 %0, t; }"
        : "=r"(a) : "l"(p));
    return a;
}
__device__ __forceinline__ uint32_t sw128(uint32_t off) {
    return off ^ ((off >> 3) & 0x70);
}
// pack two floats -> f16x2 (f0 in low half)
__device__ __forceinline__ uint32_t pkh(float f0, float f1) {
    uint32_t r;
    asm("cvt.rn.f16x2.f32 %0, %1, %2;" : "=r"(r) : "f"(f1), "f"(f0));
    return r;
}
// convert 8 floats -> fp16 uint4 (single term)
__device__ __forceinline__ void cvt8h(const float* f, uint4& h) {
    h.x = pkh(f[0], f[1]); h.y = pkh(f[2], f[3]);
    h.z = pkh(f[4], f[5]); h.w = pkh(f[6], f[7]);
}
#define LDSM4(r0, r1, r2, r3, addr)                                            \
    asm volatile("ldmatrix.sync.aligned.m8n8.x4.shared.b16 {%0,%1,%2,%3}, [%4];" \
                 : "=r"(r0), "=r"(r1), "=r"(r2), "=r"(r3) : "r"(addr))
#define MMAH(c, a, b0, b1)                                                     \
    asm volatile("mma.sync.aligned.m16n8k16.row.col.f32.f16.f16.f32 "          \
                 "{%0,%1,%2,%3}, {%4,%5,%6,%7}, {%8,%9}, {%0,%1,%2,%3};"       \
                 : "+f"((c)[0]), "+f"((c)[1]), "+f"((c)[2]), "+f"((c)[3])      \
                 : "r"((a)[0]), "r"((a)[1]), "r"((a)[2]), "r"((a)[3]),         \
                   "r"(b0), "r"(b1))
#define CPASYNC16(dst, src)                                                    \
    asm volatile("cp.async.cg.shared.global [%0], [%1], 16;"                   \
                 :: "r"(dst), "l"(src))
#define CPCOMMIT() asm volatile("cp.async.commit_group;" ::: "memory")
#define CPWAIT1()  asm volatile("cp.async.wait_group 1;" ::: "memory")
#define CPWAIT0()  asm volatile("cp.async.wait_group 0;" ::: "memory")

// ---- stage A(chunk cc) fp32 into regs (volatile -> stays sunk) ----
__device__ __forceinline__ void stage_A_fn(float stA[2][8], int cc, int tid,
                                           const float* __restrict__ encb,
                                           const float* __restrict__ pv_s) {
    if (cc < 8) {
        const float* src = encb + cc * KCH;
        #pragma unroll
        for (int i = 0; i < 2; i++) {
            int idx = tid + i * 256;
            int row = idx >> 3, g = idx & 7;
            const float* p = src + (size_t)row * ENC + g * 8;
            asm volatile("ld.global.nc.v4.f32 {%0,%1,%2,%3}, [%4];"
                : "=f"(stA[i][0]), "=f"(stA[i][1]),
                  "=f"(stA[i][2]), "=f"(stA[i][3]) : "l"(p));
            asm volatile("ld.global.nc.v4.f32 {%0,%1,%2,%3}, [%4];"
                : "=f"(stA[i][4]), "=f"(stA[i][5]),
                  "=f"(stA[i][6]), "=f"(stA[i][7]) : "l"(p + 4));
        }
    } else {
        #pragma unroll
        for (int i = 0; i < 2; i++) {
            int idx = tid + i * 256;
            int row = idx >> 3, g = idx & 7;
            #pragma unroll
            for (int j = 0; j < 8; j++) {
                int k = g * 8 + j;
                stA[i][j] = (k < KS) ? pv_s[row + k] : 0.f;
            }
        }
    }
}
// ---- convert + STS staged A into buffer `buf` (0/1) ----
__device__ __forceinline__ void sts_A_fn(float stA[2][8], int buf, int tid,
                                         char* sm) {
    #pragma unroll
    for (int i = 0; i < 2; i++) {
        int idx = tid + i * 256;
        int row = idx >> 3, g = idx & 7;
        uint4 h; cvt8h(stA[i], h);
        uint32_t off = sw128((uint32_t)(row * 128 + g * 16));
        *(uint4*)(sm + OFF_A + buf * ASTAGE + off) = h;
    }
}
// ---- issue cp.async for B(chunk cc) into ring slot cc%3 ----
__device__ __forceinline__ void fill_B_fn(int cc, int tid, uint32_t base) {
    const __half* bsrc = (cc < 8) ? g_BT : g_W2T;
    const int stride = (cc < 8) ? ENC : KCH;
    const int coff   = (cc < 8) ? cc * KCH : 0;
    const uint32_t sb = base + OFF_B + (uint32_t)(cc % 3) * BSTAGE;
    #pragma unroll
    for (int i = 0; i < 4; i++) {
        int idx = tid + i * 256;
        int n = idx >> 3, g = idx & 7;
        uint32_t off = sw128((uint32_t)(n * 128 + g * 16));
        CPASYNC16(sb + off, bsrc + (size_t)n * stride + coff + g * 8);
    }
}

// ============================ merged prep kernel ============================
// grid 144 x 256: [0,16) coalesced BT transpose (32 k-rows each);
// [16,80) W2T (k = bx-16); [80,144) qb (b = bx-80, 2-way q split).
__global__ __launch_bounds__(256)
void prep_all_kernel(const float* __restrict__ Wk,
                     const float* __restrict__ conv_w,
                     const float* __restrict__ Wl,
                     const float* __restrict__ dec,
                     const float* __restrict__ Wq,
                     const float* __restrict__ conv_b) {
    int bx = blockIdx.x, tid = threadIdx.x;
    if (bx < 16) {
        __shared__ __half st[32 * 136];           // padded rows
        int k0 = bx * 32;
        #pragma unroll
        for (int p = 0; p < 16; p++) {
            int idx = tid + p * 256;              // 0..4095
            int r = idx >> 7, n = idx & 127;
            st[r * 136 + n] = __float2half_rn(Wk[(size_t)(k0 + r) * AD + n]);
        }
        __syncthreads();
        #pragma unroll
        for (int p = 0; p < 2; p++) {
            int oidx = tid + p * 256;             // 0..511
            int kg = oidx >> 7, n = oidx & 127;   // kg: 4 groups of 8 k
            __half pack[8];
            #pragma unroll
            for (int j = 0; j < 8; j++)
                pack[j] = st[(kg * 8 + j) * 136 + n];
            *(uint4*)(g_BT + (size_t)n * ENC + k0 + kg * 8) =
                *(const uint4*)pack;
        }
    } else if (bx < 80) {
        if (tid < AD) {
            int k = bx - 16;
            float w = 0.f;
            if (k < KS) {
                #pragma unroll
                for (int c = 0; c < CH; c++)
                    w += conv_w[c * KS + k] * Wl[c * AD + tid];
            }
            g_W2T[tid * KCH + k] = __float2half_rn(w);
        }
    } else {
        __shared__ float qred[256];
        int b = bx - 80;
        int a = tid & 127, h = tid >> 7;
        float s = 0.f;
        #pragma unroll 8
        for (int q = h * 128; q < h * 128 + 128; q++)
            s += dec[b * QD + q] * Wq[q * AD + a];
        if (h == 0) {
            #pragma unroll
            for (int c = 0; c < CH; c++)
                s += conv_b[c] * Wl[c * AD + a];
        }
        qred[tid] = s;
        __syncthreads();
        if (tid < AD)
            g_qb[b * AD + tid] = qred[tid] + qred[tid + 128];
    }
}

// ============================ energy kernel ============================
// CTA: 64 t-rows x 128 attn dims; 8 warps (2m x 4n), warp tile 32x32.
// Single-term fp16; A double-buffered, B TRIPLE-buffered -> one barrier per
// chunk with no WAR aliasing: fill_B(c+2) writes slot (c+2)%3, last read by
// MMA(c-1), which is fenced by the sync at the top of iteration c.
__global__ __launch_bounds__(256, 3)
void energy_kernel(const float* __restrict__ enc,
                   const float* __restrict__ prev,
                   const float* __restrict__ v) {
    extern __shared__ char smraw[];
    const uint32_t raw = smem_u32(smraw);
    const uint32_t base = (raw + 1023u) & ~1023u;
    char* sm = smraw + (base - raw);

    const int b    = blockIdx.y;
    const int t0   = blockIdx.x * MT;
    const int tid  = threadIdx.x;
    const int lane = tid & 31;
    const int wid  = tid >> 5;
    const int warp_m = (wid >> 2) * 32;   // 2 m-tiles of 32
    const int warp_n = (wid & 3) * 32;    // 4 n-tiles of 32

    float* qb_s = (float*)(sm + OFF_QB);
    float* vv_s = (float*)(sm + OFF_VV);
    float* pv_s = (float*)(sm + OFF_PREV);
    float* part = (float*)(sm + OFF_PART);

    if (tid < AD) {
        qb_s[tid] = g_qb[b * AD + tid];
        vv_s[tid] = v[tid];
    }
    if (tid < MT + KS - 1) {
        int tg = t0 + tid - PADK;
        pv_s[tid] = (tg >= 0 && tg < T_) ? prev[b * T_ + tg] : 0.f;
    }
    // first loop sync publishes pv_s/qb/vv (pv_s first read at c=6; qb/vv epi)

    float acc[2][4][4];
    #pragma unroll
    for (int mt = 0; mt < 2; mt++)
        #pragma unroll
        for (int j = 0; j < 4; j++)
            #pragma unroll
            for (int r = 0; r < 4; r++) acc[mt][j][r] = 0.f;

    const float* encb = enc + ((size_t)b * T_ + t0) * ENC;
    float stA[2][8];

    // prologue: A(0) -> smem buf0; B(0),B(1) in flight; A(1) staged in regs
    stage_A_fn(stA, 0, tid, encb, pv_s);
    sts_A_fn(stA, 0, tid, sm);
    fill_B_fn(0, tid, base); CPCOMMIT();
    fill_B_fn(1, tid, base); CPCOMMIT();
    stage_A_fn(stA, 1, tid, encb, pv_s);

    for (int c = 0; c < NCHUNK; c++) {
        if (c < 8) CPWAIT1(); else CPWAIT0();   // B(c) complete
        __syncthreads();   // A(c) STS visible; all MMA(c-1) done
        const uint32_t aa = base + OFF_A + (uint32_t)(c & 1) * ASTAGE;
        const uint32_t bb = base + OFF_B + (uint32_t)(c % 3) * BSTAGE;
        // ---- mma over this chunk: 4 k16 steps; 4 LDSM + 8 MMA per kk ----
        #pragma unroll
        for (int kk = 0; kk < 4; kk++) {
            const uint32_t kb  = (uint32_t)(kk * 32) + ((lane >> 4) & 1) * 16;
            const uint32_t kbb = (uint32_t)(kk * 32) + ((lane >> 3) & 1) * 16;
            uint32_t ah[2][4];
            uint32_t bf[2][4];
            #pragma unroll
            for (int mt = 0; mt < 2; mt++) {
                int row = warp_m + mt * 16 + (lane & 15);
                uint32_t off = sw128((uint32_t)(row * 128) + kb);
                LDSM4(ah[mt][0], ah[mt][1], ah[mt][2], ah[mt][3], aa + off);
            }
            #pragma unroll
            for (int q = 0; q < 2; q++) {
                int n = warp_n + q * 16 + ((lane >> 4) << 3) + (lane & 7);
                uint32_t off = sw128((uint32_t)(n * 128) + kbb);
                LDSM4(bf[q][0], bf[q][1], bf[q][2], bf[q][3], bb + off);
            }
            #pragma unroll
            for (int mt = 0; mt < 2; mt++) {
                #pragma unroll
                for (int q = 0; q < 2; q++) {
                    MMAH(acc[mt][q * 2],     ah[mt], bf[q][0], bf[q][1]);
                    MMAH(acc[mt][q * 2 + 1], ah[mt], bf[q][2], bf[q][3]);
                }
            }
        }
        // ---- post-MMA (unfenced; targets fenced by NEXT sync are safe):
        // STS A(c+1) -> Abuf[(c+1)&1] (last read MMA(c-1), fenced by sync(c));
        // fill_B(c+2) -> Bslot[(c+2)%3] (last read MMA(c-1), fenced). ----
        if (c < 8) {
            sts_A_fn(stA, (c + 1) & 1, tid, sm);
            if (c < 7) {
                fill_B_fn(c + 2, tid, base); CPCOMMIT();
                stage_A_fn(stA, c + 2, tid, encb, pv_s);
            }
        }
    }

    // ---- epilogue: tanh + dot(v) + reduce ----
    float pr[4] = {0.f, 0.f, 0.f, 0.f};
    #pragma unroll
    for (int mt = 0; mt < 2; mt++) {
        #pragma unroll
        for (int j = 0; j < 4; j++) {
            int n0 = warp_n + j * 8 + 2 * (lane & 3);
            float v0 = vv_s[n0], v1 = vv_s[n0 + 1];
            float q0 = qb_s[n0], q1 = qb_s[n0 + 1];
            #pragma unroll
            for (int rh = 0; rh < 2; rh++) {
                float x0 = acc[mt][j][rh * 2]     + q0;
                float x1 = acc[mt][j][rh * 2 + 1] + q1;
                x0 = fminf(fmaxf(x0, -15.f), 15.f);
                x1 = fminf(fmaxf(x1, -15.f), 15.f);
                float e0 = __expf(2.f * x0), e1 = __expf(2.f * x1);
                float th0 = (e0 - 1.f) * __frcp_rn(e0 + 1.f);
                float th1 = (e1 - 1.f) * __frcp_rn(e1 + 1.f);
                pr[mt * 2 + rh] += th0 * v0 + th1 * v1;
            }
        }
    }
    #pragma unroll
    for (int i = 0; i < 4; i++) {
        pr[i] += __shfl_xor_sync(0xffffffffu, pr[i], 1);
        pr[i] += __shfl_xor_sync(0xffffffffu, pr[i], 2);
    }
    const int wn = wid & 3;
    if ((lane & 3) == 0) {
        int rbase = warp_m + (lane >> 2);
        part[wn * MT + rbase]      = pr[0];
        part[wn * MT + rbase + 8]  = pr[1];
        part[wn * MT + rbase + 16] = pr[2];
        part[wn * MT + rbase + 24] = pr[3];
    }
    __syncthreads();
    if (tid < MT)
        g_energy[b * T_ + t0 + tid] = part[tid] + part[MT + tid]
                                    + part[2 * MT + tid] + part[3 * MT + tid];
}

// ============================ softmax ============================
__global__ __launch_bounds__(512)
void softmax_kernel(float* __restrict__ out) {
    __shared__ float red[16];
    const int b = blockIdx.x, tid = threadIdx.x;
    const int lane = tid & 31, warp = tid >> 5;
    const float4* e4 = (const float4*)(g_energy + b * T_);
    float4 f = e4[tid];

    float mx = fmaxf(fmaxf(f.x, f.y), fmaxf(f.z, f.w));
    #pragma unroll
    for (int o = 16; o; o >>= 1)
        mx = fmaxf(mx, __shfl_xor_sync(0xffffffffu, mx, o));
    if (lane == 0) red[warp] = mx;
    __syncthreads();
    mx = red[lane & 15];
    #pragma unroll
    for (int o = 8; o; o >>= 1)
        mx = fmaxf(mx, __shfl_xor_sync(0xffffffffu, mx, o));

    float4 ex;
    ex.x = __expf(f.x - mx); ex.y = __expf(f.y - mx);
    ex.z = __expf(f.z - mx); ex.w = __expf(f.w - mx);
    float sum = ex.x + ex.y + ex.z + ex.w;
    #pragma unroll
    for (int o = 16; o; o >>= 1)
        sum += __shfl_xor_sync(0xffffffffu, sum, o);
    __syncthreads();
    if (lane == 0) red[warp] = sum;
    __syncthreads();
    sum = red[lane & 15];
    #pragma unroll
    for (int o = 8; o; o >>= 1)
        sum += __shfl_xor_sync(0xffffffffu, sum, o);
    float inv = 1.f / sum;

    float4 o4; o4.x = ex.x*inv; o4.y = ex.y*inv; o4.z = ex.z*inv; o4.w = ex.w*inv;
    ((float4*)(out + b * T_))[tid] = o4;
}

// ============================ launch ============================
extern "C" void kernel_launch(void* const* d_in, const int* in_sizes, int n_in,
                              void* d_out, int out_size) {
    const float* enc    = (const float*)d_in[0];
    const float* dec    = (const float*)d_in[1];
    const float* prev   = (const float*)d_in[2];
    const float* Wq     = (const float*)d_in[3];
    const float* Wk     = (const float*)d_in[4];
    const float* conv_w = (const float*)d_in[5];
    const float* conv_b = (const float*)d_in[6];
    const float* Wl     = (const float*)d_in[7];
    const float* v      = (const float*)d_in[8];
    float* out = (float*)d_out;

    cudaFuncSetAttribute(energy_kernel,
                         cudaFuncAttributeMaxDynamicSharedMemorySize, SMEM_REQ);

    prep_all_kernel<<<144, 256>>>(Wk, conv_w, Wl, dec, Wq, conv_b);
    energy_kernel<<<dim3(T_ / MT, B_), 256, SMEM_REQ>>>(enc, prev, v);
    softmax_kernel<<<B_, 512>>>(out);
}

// round 16
// speedup vs baseline: 4.6881x; 1.0827x over previous
#include <cuda_runtime.h>
#include <cuda_fp16.h>
#include <cstdint>
#include <math.h>

#define B_    64
#define T_    2048
#define ENC   512
#define QD    256
#define AD    128
#define CH    32
#define KS    31
#define PADK  15

#define MT     64       // t-rows per CTA (3 CTAs/SM)
#define KCH    64       // k per chunk (64 fp16 = 128B rows, SW128)
#define NCHUNK 9        // 8 enc chunks + 1 location chunk

// ---- dynamic smem layout (relative to 1024-aligned base) ----
#define OFF_A    0              // two stages of 8 KB (A single-term fp16)
#define ASTAGE   8192
#define OFF_B    16384          // THREE stages of 16 KB (B single fp16)
#define BSTAGE   16384
#define OFF_QB   65536          // 128 floats
#define OFF_VV   (OFF_QB + 512)
#define OFF_PREV (OFF_VV + 512)   // 94 floats (pad 384)
#define OFF_PART (OFF_PREV + 384) // 4*64 floats = 1024B
#define SMEM_REQ (OFF_PART + 1024 + 2048)   // + alignment slack (~69.5 KB)

// ---- device scratch ----
__device__ __align__(16) float g_energy[B_ * T_];
__device__ float         g_qb[B_ * AD];
__device__ __align__(16) __half g_BT[AD * ENC];      // Wk^T, K-major fp16
__device__ __align__(16) __half g_W2T[AD * KCH];     // W2^T fp16

// ============================ helpers ============================
__device__ __forceinline__ uint32_t smem_u32(const void* p) {
    uint32_t a;
    asm("{ .reg .u64 t; cvta.to.shared.u64 t, %1; cvt.u32.u64 %0, t; }"
        : "=r"(a) : "l"(p));
    return a;
}
__device__ __forceinline__ uint32_t sw128(uint32_t off) {
    return off ^ ((off >> 3) & 0x70);
}
// pack two floats -> f16x2 (f0 in low half)
__device__ __forceinline__ uint32_t pkh(float f0, float f1) {
    uint32_t r;
    asm("cvt.rn.f16x2.f32 %0, %1, %2;" : "=r"(r) : "f"(f1), "f"(f0));
    return r;
}
// convert 8 floats -> fp16 uint4 (single term)
__device__ __forceinline__ void cvt8h(const float* f, uint4& h) {
    h.x = pkh(f[0], f[1]); h.y = pkh(f[2], f[3]);
    h.z = pkh(f[4], f[5]); h.w = pkh(f[6], f[7]);
}
#define LDSM4(r0, r1, r2, r3, addr)                                            \
    asm volatile("ldmatrix.sync.aligned.m8n8.x4.shared.b16 {%0,%1,%2,%3}, [%4];" \
                 : "=r"(r0), "=r"(r1), "=r"(r2), "=r"(r3) : "r"(addr))
#define MMAH(c, a, b0, b1)                                                     \
    asm volatile("mma.sync.aligned.m16n8k16.row.col.f32.f16.f16.f32 "          \
                 "{%0,%1,%2,%3}, {%4,%5,%6,%7}, {%8,%9}, {%0,%1,%2,%3};"       \
                 : "+f"((c)[0]), "+f"((c)[1]), "+f"((c)[2]), "+f"((c)[3])      \
                 : "r"((a)[0]), "r"((a)[1]), "r"((a)[2]), "r"((a)[3]),         \
                   "r"(b0), "r"(b1))
#define CPASYNC16(dst, src)                                                    \
    asm volatile("cp.async.cg.shared.global [%0], [%1], 16;"                   \
                 :: "r"(dst), "l"(src))
#define CPCOMMIT() asm volatile("cp.async.commit_group;" ::: "memory")
#define CPWAIT1()  asm volatile("cp.async.wait_group 1;" ::: "memory")
#define CPWAIT0()  asm volatile("cp.async.wait_group 0;" ::: "memory")

// ---- stage A(chunk cc) fp32 into regs (volatile -> stays sunk) ----
__device__ __forceinline__ void stage_A_fn(float stA[2][8], int cc, int tid,
                                           const float* __restrict__ encb,
                                           const float* __restrict__ pv_s) {
    if (cc < 8) {
        const float* src = encb + cc * KCH;
        #pragma unroll
        for (int i = 0; i < 2; i++) {
            int idx = tid + i * 256;
            int row = idx >> 3, g = idx & 7;
            const float* p = src + (size_t)row * ENC + g * 8;
            asm volatile("ld.global.nc.v4.f32 {%0,%1,%2,%3}, [%4];"
                : "=f"(stA[i][0]), "=f"(stA[i][1]),
                  "=f"(stA[i][2]), "=f"(stA[i][3]) : "l"(p));
            asm volatile("ld.global.nc.v4.f32 {%0,%1,%2,%3}, [%4];"
                : "=f"(stA[i][4]), "=f"(stA[i][5]),
                  "=f"(stA[i][6]), "=f"(stA[i][7]) : "l"(p + 4));
        }
    } else {
        #pragma unroll
        for (int i = 0; i < 2; i++) {
            int idx = tid + i * 256;
            int row = idx >> 3, g = idx & 7;
            #pragma unroll
            for (int j = 0; j < 8; j++) {
                int k = g * 8 + j;
                stA[i][j] = (k < KS) ? pv_s[row + k] : 0.f;
            }
        }
    }
}
// ---- convert + STS staged A into buffer `buf` (0/1) ----
__device__ __forceinline__ void sts_A_fn(float stA[2][8], int buf, int tid,
                                         char* sm) {
    #pragma unroll
    for (int i = 0; i < 2; i++) {
        int idx = tid + i * 256;
        int row = idx >> 3, g = idx & 7;
        uint4 h; cvt8h(stA[i], h);
        uint32_t off = sw128((uint32_t)(row * 128 + g * 16));
        *(uint4*)(sm + OFF_A + buf * ASTAGE + off) = h;
    }
}
// ---- issue cp.async for B(chunk cc) into ring slot cc%3 ----
__device__ __forceinline__ void fill_B_fn(int cc, int tid, uint32_t base) {
    const __half* bsrc = (cc < 8) ? g_BT : g_W2T;
    const int stride = (cc < 8) ? ENC : KCH;
    const int coff   = (cc < 8) ? cc * KCH : 0;
    const uint32_t sb = base + OFF_B + (uint32_t)(cc % 3) * BSTAGE;
    #pragma unroll
    for (int i = 0; i < 4; i++) {
        int idx = tid + i * 256;
        int n = idx >> 3, g = idx & 7;
        uint32_t off = sw128((uint32_t)(n * 128 + g * 16));
        CPASYNC16(sb + off, bsrc + (size_t)n * stride + coff + g * 8);
    }
}

// ============================ merged prep kernel ============================
// grid 160 x 512:
//   [0,32):   BT transpose, 16 k-rows each (4 smem-load iters, 256 writers)
//   [32,96):  W2T (k = bx-32), first 128 threads
//   [96,160): qb (b = bx-96), 4-way q split + smem reduce
__global__ __launch_bounds__(512)
void prep_all_kernel(const float* __restrict__ Wk,
                     const float* __restrict__ conv_w,
                     const float* __restrict__ Wl,
                     const float* __restrict__ dec,
                     const float* __restrict__ Wq,
                     const float* __restrict__ conv_b) {
    int bx = blockIdx.x, tid = threadIdx.x;
    if (bx < 32) {
        __shared__ __half st[16 * 136];           // padded rows
        int k0 = bx * 16;
        #pragma unroll
        for (int p = 0; p < 4; p++) {
            int idx = tid + p * 512;              // 0..2047
            int r = idx >> 7, n = idx & 127;
            st[r * 136 + n] = __float2half_rn(Wk[(size_t)(k0 + r) * AD + n]);
        }
        __syncthreads();
        if (tid < 256) {
            int kg = tid >> 7, n = tid & 127;     // 2 groups of 8 k
            __half pack[8];
            #pragma unroll
            for (int j = 0; j < 8; j++)
                pack[j] = st[(kg * 8 + j) * 136 + n];
            *(uint4*)(g_BT + (size_t)n * ENC + k0 + kg * 8) =
                *(const uint4*)pack;
        }
    } else if (bx < 96) {
        if (tid < AD) {
            int k = bx - 32;
            float w = 0.f;
            if (k < KS) {
                #pragma unroll
                for (int c = 0; c < CH; c++)
                    w += conv_w[c * KS + k] * Wl[c * AD + tid];
            }
            g_W2T[tid * KCH + k] = __float2half_rn(w);
        }
    } else {
        __shared__ float qred[512];
        int b = bx - 96;
        int a = tid & 127, h = tid >> 7;          // 4-way q split
        float s = 0.f;
        #pragma unroll 8
        for (int q = h * 64; q < h * 64 + 64; q++)
            s += dec[b * QD + q] * Wq[q * AD + a];
        if (h == 0) {
            #pragma unroll
            for (int c = 0; c < CH; c++)
                s += conv_b[c] * Wl[c * AD + a];
        }
        qred[tid] = s;
        __syncthreads();
        if (tid < AD)
            g_qb[b * AD + tid] = (qred[tid] + qred[tid + 128])
                               + (qred[tid + 256] + qred[tid + 384]);
    }
}

// ============================ energy kernel ============================
// CTA: 64 t-rows x 128 attn dims; 8 warps (2m x 4n), warp tile 32x32.
// Single-term fp16; A double-buffered, B TRIPLE-buffered -> one barrier per
// chunk with no WAR aliasing (UNCHANGED from R14 — proven correct/fast).
__global__ __launch_bounds__(256, 3)
void energy_kernel(const float* __restrict__ enc,
                   const float* __restrict__ prev,
                   const float* __restrict__ v) {
    extern __shared__ char smraw[];
    const uint32_t raw = smem_u32(smraw);
    const uint32_t base = (raw + 1023u) & ~1023u;
    char* sm = smraw + (base - raw);

    const int b    = blockIdx.y;
    const int t0   = blockIdx.x * MT;
    const int tid  = threadIdx.x;
    const int lane = tid & 31;
    const int wid  = tid >> 5;
    const int warp_m = (wid >> 2) * 32;   // 2 m-tiles of 32
    const int warp_n = (wid & 3) * 32;    // 4 n-tiles of 32

    float* qb_s = (float*)(sm + OFF_QB);
    float* vv_s = (float*)(sm + OFF_VV);
    float* pv_s = (float*)(sm + OFF_PREV);
    float* part = (float*)(sm + OFF_PART);

    if (tid < AD) {
        qb_s[tid] = g_qb[b * AD + tid];
        vv_s[tid] = v[tid];
    }
    if (tid < MT + KS - 1) {
        int tg = t0 + tid - PADK;
        pv_s[tid] = (tg >= 0 && tg < T_) ? prev[b * T_ + tg] : 0.f;
    }
    // first loop sync publishes pv_s/qb/vv (pv_s first read at c=6; qb/vv epi)

    float acc[2][4][4];
    #pragma unroll
    for (int mt = 0; mt < 2; mt++)
        #pragma unroll
        for (int j = 0; j < 4; j++)
            #pragma unroll
            for (int r = 0; r < 4; r++) acc[mt][j][r] = 0.f;

    const float* encb = enc + ((size_t)b * T_ + t0) * ENC;
    float stA[2][8];

    // prologue: A(0) -> smem buf0; B(0),B(1) in flight; A(1) staged in regs
    stage_A_fn(stA, 0, tid, encb, pv_s);
    sts_A_fn(stA, 0, tid, sm);
    fill_B_fn(0, tid, base); CPCOMMIT();
    fill_B_fn(1, tid, base); CPCOMMIT();
    stage_A_fn(stA, 1, tid, encb, pv_s);

    for (int c = 0; c < NCHUNK; c++) {
        if (c < 8) CPWAIT1(); else CPWAIT0();   // B(c) complete
        __syncthreads();   // A(c) STS visible; all MMA(c-1) done
        const uint32_t aa = base + OFF_A + (uint32_t)(c & 1) * ASTAGE;
        const uint32_t bb = base + OFF_B + (uint32_t)(c % 3) * BSTAGE;
        // ---- mma over this chunk: 4 k16 steps; 4 LDSM + 8 MMA per kk ----
        #pragma unroll
        for (int kk = 0; kk < 4; kk++) {
            const uint32_t kb  = (uint32_t)(kk * 32) + ((lane >> 4) & 1) * 16;
            const uint32_t kbb = (uint32_t)(kk * 32) + ((lane >> 3) & 1) * 16;
            uint32_t ah[2][4];
            uint32_t bf[2][4];
            #pragma unroll
            for (int mt = 0; mt < 2; mt++) {
                int row = warp_m + mt * 16 + (lane & 15);
                uint32_t off = sw128((uint32_t)(row * 128) + kb);
                LDSM4(ah[mt][0], ah[mt][1], ah[mt][2], ah[mt][3], aa + off);
            }
            #pragma unroll
            for (int q = 0; q < 2; q++) {
                int n = warp_n + q * 16 + ((lane >> 4) << 3) + (lane & 7);
                uint32_t off = sw128((uint32_t)(n * 128) + kbb);
                LDSM4(bf[q][0], bf[q][1], bf[q][2], bf[q][3], bb + off);
            }
            #pragma unroll
            for (int mt = 0; mt < 2; mt++) {
                #pragma unroll
                for (int q = 0; q < 2; q++) {
                    MMAH(acc[mt][q * 2],     ah[mt], bf[q][0], bf[q][1]);
                    MMAH(acc[mt][q * 2 + 1], ah[mt], bf[q][2], bf[q][3]);
                }
            }
        }
        // ---- post-MMA (unfenced; targets fenced by sync(c) are safe) ----
        if (c < 8) {
            sts_A_fn(stA, (c + 1) & 1, tid, sm);
            if (c < 7) {
                fill_B_fn(c + 2, tid, base); CPCOMMIT();
                stage_A_fn(stA, c + 2, tid, encb, pv_s);
            }
        }
    }

    // ---- epilogue: tanh + dot(v) + reduce ----
    float pr[4] = {0.f, 0.f, 0.f, 0.f};
    #pragma unroll
    for (int mt = 0; mt < 2; mt++) {
        #pragma unroll
        for (int j = 0; j < 4; j++) {
            int n0 = warp_n + j * 8 + 2 * (lane & 3);
            float v0 = vv_s[n0], v1 = vv_s[n0 + 1];
            float q0 = qb_s[n0], q1 = qb_s[n0 + 1];
            #pragma unroll
            for (int rh = 0; rh < 2; rh++) {
                float x0 = acc[mt][j][rh * 2]     + q0;
                float x1 = acc[mt][j][rh * 2 + 1] + q1;
                x0 = fminf(fmaxf(x0, -15.f), 15.f);
                x1 = fminf(fmaxf(x1, -15.f), 15.f);
                float e0 = __expf(2.f * x0), e1 = __expf(2.f * x1);
                float th0 = (e0 - 1.f) * __frcp_rn(e0 + 1.f);
                float th1 = (e1 - 1.f) * __frcp_rn(e1 + 1.f);
                pr[mt * 2 + rh] += th0 * v0 + th1 * v1;
            }
        }
    }
    #pragma unroll
    for (int i = 0; i < 4; i++) {
        pr[i] += __shfl_xor_sync(0xffffffffu, pr[i], 1);
        pr[i] += __shfl_xor_sync(0xffffffffu, pr[i], 2);
    }
    const int wn = wid & 3;
    if ((lane & 3) == 0) {
        int rbase = warp_m + (lane >> 2);
        part[wn * MT + rbase]      = pr[0];
        part[wn * MT + rbase + 8]  = pr[1];
        part[wn * MT + rbase + 16] = pr[2];
        part[wn * MT + rbase + 24] = pr[3];
    }
    __syncthreads();
    if (tid < MT)
        g_energy[b * T_ + t0 + tid] = part[tid] + part[MT + tid]
                                    + part[2 * MT + tid] + part[3 * MT + tid];
}

// ============================ softmax ============================
__global__ __launch_bounds__(512)
void softmax_kernel(float* __restrict__ out) {
    __shared__ float red[16];
    const int b = blockIdx.x, tid = threadIdx.x;
    const int lane = tid & 31, warp = tid >> 5;
    const float4* e4 = (const float4*)(g_energy + b * T_);
    float4 f = e4[tid];

    float mx = fmaxf(fmaxf(f.x, f.y), fmaxf(f.z, f.w));
    #pragma unroll
    for (int o = 16; o; o >>= 1)
        mx = fmaxf(mx, __shfl_xor_sync(0xffffffffu, mx, o));
    if (lane == 0) red[warp] = mx;
    __syncthreads();
    mx = red[lane & 15];
    #pragma unroll
    for (int o = 8; o; o >>= 1)
        mx = fmaxf(mx, __shfl_xor_sync(0xffffffffu, mx, o));

    float4 ex;
    ex.x = __expf(f.x - mx); ex.y = __expf(f.y - mx);
    ex.z = __expf(f.z - mx); ex.w = __expf(f.w - mx);
    float sum = ex.x + ex.y + ex.z + ex.w;
    #pragma unroll
    for (int o = 16; o; o >>= 1)
        sum += __shfl_xor_sync(0xffffffffu, sum, o);
    __syncthreads();
    if (lane == 0) red[warp] = sum;
    __syncthreads();
    sum = red[lane & 15];
    #pragma unroll
    for (int o = 8; o; o >>= 1)
        sum += __shfl_xor_sync(0xffffffffu, sum, o);
    float inv = 1.f / sum;

    float4 o4; o4.x = ex.x*inv; o4.y = ex.y*inv; o4.z = ex.z*inv; o4.w = ex.w*inv;
    ((float4*)(out + b * T_))[tid] = o4;
}

// ============================ launch ============================
extern "C" void kernel_launch(void* const* d_in, const int* in_sizes, int n_in,
                              void* d_out, int out_size) {
    const float* enc    = (const float*)d_in[0];
    const float* dec    = (const float*)d_in[1];
    const float* prev   = (const float*)d_in[2];
    const float* Wq     = (const float*)d_in[3];
    const float* Wk     = (const float*)d_in[4];
    const float* conv_w = (const float*)d_in[5];
    const float* conv_b = (const float*)d_in[6];
    const float* Wl     = (const float*)d_in[7];
    const float* v      = (const float*)d_in[8];
    float* out = (float*)d_out;

    cudaFuncSetAttribute(energy_kernel,
                         cudaFuncAttributeMaxDynamicSharedMemorySize, SMEM_REQ);

    prep_all_kernel<<<160, 512>>>(Wk, conv_w, Wl, dec, Wq, conv_b);
    energy_kernel<<<dim3(T_ / MT, B_), 256, SMEM_REQ>>>(enc, prev, v);
    softmax_kernel<<<B_, 512>>>(out);
}